// round 5
// baseline (speedup 1.0000x reference)
#include <cuda_runtime.h>
#include <math.h>

// Problem constants
#define BSZ   4
#define TLEN  1024
#define DDIM  1024
#define NH    16
#define DH    64
#define LPOS  128
#define NPOS  257            // 2*L+1
#define QPS   272            // padded stride for Qp rows
#define INV_SCALE 0.125f     // 1/sqrt(D/H) = 1/8

// -------- device scratch (no allocations allowed) --------
__device__ float g_Q [BSZ*TLEN*DDIM];
__device__ float g_K [BSZ*TLEN*DDIM];
__device__ float g_V [BSZ*TLEN*DDIM];
__device__ float g_O [BSZ*TLEN*DDIM];
__device__ float g_Qp[BSZ*NH*TLEN*QPS];
__device__ unsigned char g_mask[BSZ*TLEN];

// ============================================================
// mask_prep: normalize the mask input to uint8 {0,1}.
// The reference mask is a bool array; the harness may store it as
// int32 (widened) or as 1-byte bools. Detect on-device:
//   int32 {0,1} little-endian => every byte at (i%4 != 0) is zero.
//   byte bools (random 0/1)   => ~37% of those bytes are 1.
// Detection reads only the first BSZ*TLEN bytes, valid under both
// interpretations. Deterministic for fixed input.
// ============================================================
__global__ void mask_prep(const unsigned char* __restrict__ mraw)
{
    __shared__ int s_bytefmt;
    if (threadIdx.x == 0) s_bytefmt = 0;
    __syncthreads();

    int local = 0;
    for (int i = threadIdx.x; i < BSZ*TLEN; i += blockDim.x)
        if ((i & 3) != 0 && mraw[i] != 0) local = 1;
    if (local) atomicOr(&s_bytefmt, 1);
    __syncthreads();

    if (s_bytefmt) {
        for (int i = threadIdx.x; i < BSZ*TLEN; i += blockDim.x)
            g_mask[i] = mraw[i] ? 1 : 0;
    } else {
        const int* mi = (const int*)mraw;
        for (int i = threadIdx.x; i < BSZ*TLEN; i += blockDim.x)
            g_mask[i] = mi[i] ? 1 : 0;
    }
}

// ============================================================
// SGEMM NT: C[M,N] = A[M,K] * B[N,K]^T   (row-major, fp32)
// BM=BN=128, BK=16, 256 threads, 8x8 microtile
// ============================================================
__global__ void __launch_bounds__(256) sgemm_nt(
    const float* __restrict__ A, const float* __restrict__ Bm,
    float* __restrict__ C, int M, int N, int K)
{
    __shared__ float As[16][128];
    __shared__ float Bs[16][128];

    const int tid = threadIdx.x;
    const int tx = tid & 15;      // -> n
    const int ty = tid >> 4;      // -> m
    const int m0 = blockIdx.y * 128;
    const int n0 = blockIdx.x * 128;

    const int lrow = tid >> 1;          // 0..127
    const int lk4  = (tid & 1) * 2;     // float4 slot 0 or 2

    float c[8][8];
#pragma unroll
    for (int i = 0; i < 8; i++)
#pragma unroll
        for (int j = 0; j < 8; j++) c[i][j] = 0.0f;

    for (int k0 = 0; k0 < K; k0 += 16) {
        const float4* Ap = (const float4*)(A  + (size_t)(m0 + lrow) * K + k0);
        const float4* Bp = (const float4*)(Bm + (size_t)(n0 + lrow) * K + k0);
        float4 a0 = Ap[lk4], a1 = Ap[lk4 + 1];
        float4 b0 = Bp[lk4], b1 = Bp[lk4 + 1];
        __syncthreads();
        int kb = lk4 * 4;
        As[kb+0][lrow]=a0.x; As[kb+1][lrow]=a0.y; As[kb+2][lrow]=a0.z; As[kb+3][lrow]=a0.w;
        As[kb+4][lrow]=a1.x; As[kb+5][lrow]=a1.y; As[kb+6][lrow]=a1.z; As[kb+7][lrow]=a1.w;
        Bs[kb+0][lrow]=b0.x; Bs[kb+1][lrow]=b0.y; Bs[kb+2][lrow]=b0.z; Bs[kb+3][lrow]=b0.w;
        Bs[kb+4][lrow]=b1.x; Bs[kb+5][lrow]=b1.y; Bs[kb+6][lrow]=b1.z; Bs[kb+7][lrow]=b1.w;
        __syncthreads();
#pragma unroll
        for (int kk = 0; kk < 16; kk++) {
            float a[8], b[8];
            *(float4*)(a)     = *(const float4*)&As[kk][ty*8];
            *(float4*)(a + 4) = *(const float4*)&As[kk][ty*8 + 4];
            *(float4*)(b)     = *(const float4*)&Bs[kk][tx*8];
            *(float4*)(b + 4) = *(const float4*)&Bs[kk][tx*8 + 4];
#pragma unroll
            for (int i = 0; i < 8; i++)
#pragma unroll
                for (int j = 0; j < 8; j++)
                    c[i][j] = fmaf(a[i], b[j], c[i][j]);
        }
    }

#pragma unroll
    for (int i = 0; i < 8; i++) {
        float* crow = C + (size_t)(m0 + ty*8 + i) * N + n0 + tx*8;
        float4 v0 = make_float4(c[i][0], c[i][1], c[i][2], c[i][3]);
        float4 v1 = make_float4(c[i][4], c[i][5], c[i][6], c[i][7]);
        *(float4*)(crow)     = v0;
        *(float4*)(crow + 4) = v1;
    }
}

// ============================================================
// Qp[b,h,q,r] = sum_d Q[b,q,h*DH+d] * pos_emb[r,d]
// one block per (b, h, q-tile of 64); 256 threads
// dyn smem: Qs[64*64] + Ps[257*65]
// ============================================================
#define QP_SMEM ((64*64 + NPOS*65) * 4)
__global__ void __launch_bounds__(256) qp_kernel(const float* __restrict__ pos_emb)
{
    extern __shared__ float sm[];
    float* Qs = sm;              // [q][d] stride 64
    float* Ps = sm + 64*64;      // [r][d] stride 65

    const int blk = blockIdx.x;
    const int qt = blk & 15, h = (blk >> 4) & 15, b = blk >> 8;
    const int q0 = qt * 64;
    const int tid = threadIdx.x;

    for (int i = tid; i < 64*64; i += 256) {
        int q = i >> 6, d = i & 63;
        Qs[q*64 + d] = g_Q[(size_t)(b*TLEN + q0 + q)*DDIM + h*DH + d];
    }
    for (int i = tid; i < NPOS*DH; i += 256) {
        int r = i >> 6, d = i & 63;
        Ps[r*65 + d] = pos_emb[i];
    }
    __syncthreads();

    const int rowbase = (b*NH + h)*TLEN + q0;
    for (int idx = tid; idx < 64*NPOS; idx += 256) {
        int q = idx / NPOS;
        int r = idx - q*NPOS;
        const float* qr = Qs + q*64;
        const float* pr = Ps + r*65;
        float s = 0.0f;
#pragma unroll 16
        for (int d = 0; d < 64; d++) s = fmaf(qr[d], pr[d], s);
        g_Qp[(size_t)(rowbase + q)*QPS + r] = s;
    }
}

// ============================================================
// Flash-style attention: one block per (b, h, q-tile of 64)
// 256 threads: tx (0..15) -> 4 k/d cols, ty (0..15) -> 4 q rows
// dyn smem: QsT/KsT/Vs/PsT, each [64][68]
// ============================================================
#define AT_STRIDE 68
#define AT_SMEM (4 * 64 * AT_STRIDE * 4)
__global__ void __launch_bounds__(256) attn_kernel()
{
    extern __shared__ float sm[];
    float* QsT = sm;                     // [d][q]
    float* KsT = QsT + 64*AT_STRIDE;     // [d][k]
    float* Vs  = KsT + 64*AT_STRIDE;     // [k][d]
    float* PsT = Vs  + 64*AT_STRIDE;     // [k][q]

    const int blk = blockIdx.x;
    const int qt = blk & 15, h = (blk >> 4) & 15, b = blk >> 8;
    const int q0 = qt * 64;
    const int tid = threadIdx.x;
    const int tx = tid & 15, ty = tid >> 4;

    // load Q tile transposed
    for (int i = tid; i < 64*64; i += 256) {
        int q = i >> 6, d = i & 63;
        QsT[d*AT_STRIDE + q] = g_Q[(size_t)(b*TLEN + q0 + q)*DDIM + h*DH + d];
    }

    float m[4], l[4], o[4][4];
#pragma unroll
    for (int i = 0; i < 4; i++) {
        m[i] = -1e30f; l[i] = 0.0f;
#pragma unroll
        for (int j = 0; j < 4; j++) o[i][j] = 0.0f;
    }

    const int qp_rowbase = (b*NH + h)*TLEN + q0;

    for (int kt = 0; kt < 16; kt++) {
        const int k0 = kt * 64;
        __syncthreads();
        for (int i = tid; i < 64*64; i += 256) {
            int k = i >> 6, d = i & 63;
            size_t gidx = (size_t)(b*TLEN + k0 + k)*DDIM + h*DH + d;
            KsT[d*AT_STRIDE + k] = g_K[gidx];
            Vs [k*AT_STRIDE + d] = g_V[gidx];
        }
        __syncthreads();

        // S = Q K^T (4x4 per thread)
        float s[4][4];
#pragma unroll
        for (int i = 0; i < 4; i++)
#pragma unroll
            for (int j = 0; j < 4; j++) s[i][j] = 0.0f;
#pragma unroll 8
        for (int d = 0; d < 64; d++) {
            float a[4], bb[4];
            *(float4*)a  = *(const float4*)&QsT[d*AT_STRIDE + ty*4];
            *(float4*)bb = *(const float4*)&KsT[d*AT_STRIDE + tx*4];
#pragma unroll
            for (int i = 0; i < 4; i++)
#pragma unroll
                for (int j = 0; j < 4; j++)
                    s[i][j] = fmaf(a[i], bb[j], s[i][j]);
        }

        // mask bytes for this thread's 4 k columns (normalized uint8)
        unsigned char mk[4];
#pragma unroll
        for (int j = 0; j < 4; j++) mk[j] = g_mask[b*TLEN + k0 + tx*4 + j];

        // pos gather + scale + mask
#pragma unroll
        for (int i = 0; i < 4; i++) {
            const int q = q0 + ty*4 + i;
            const float* qpr = g_Qp + (size_t)(qp_rowbase + ty*4 + i)*QPS;
#pragma unroll
            for (int j = 0; j < 4; j++) {
                int k = k0 + tx*4 + j;
                int r = k - q;
                r = r < -LPOS ? -LPOS : (r > LPOS ? LPOS : r);
                float v = (s[i][j] + qpr[r + LPOS]) * INV_SCALE;
                s[i][j] = mk[j] ? -1e30f : v;
            }
        }

        // online softmax (reduce across tx = 16-lane half-warp)
#pragma unroll
        for (int i = 0; i < 4; i++) {
            float rm = s[i][0];
#pragma unroll
            for (int j = 1; j < 4; j++) rm = fmaxf(rm, s[i][j]);
            rm = fmaxf(rm, __shfl_xor_sync(0xffffffffu, rm, 8));
            rm = fmaxf(rm, __shfl_xor_sync(0xffffffffu, rm, 4));
            rm = fmaxf(rm, __shfl_xor_sync(0xffffffffu, rm, 2));
            rm = fmaxf(rm, __shfl_xor_sync(0xffffffffu, rm, 1));
            float mnew = fmaxf(m[i], rm);
            float alpha = __expf(m[i] - mnew);
            float p[4], rs = 0.0f;
#pragma unroll
            for (int j = 0; j < 4; j++) { p[j] = __expf(s[i][j] - mnew); rs += p[j]; }
            rs += __shfl_xor_sync(0xffffffffu, rs, 8);
            rs += __shfl_xor_sync(0xffffffffu, rs, 4);
            rs += __shfl_xor_sync(0xffffffffu, rs, 2);
            rs += __shfl_xor_sync(0xffffffffu, rs, 1);
            l[i] = l[i]*alpha + rs;
            m[i] = mnew;
#pragma unroll
            for (int j = 0; j < 4; j++) PsT[(tx*4 + j)*AT_STRIDE + ty*4 + i] = p[j];
#pragma unroll
            for (int j = 0; j < 4; j++) o[i][j] *= alpha;
        }
        __syncthreads();

        // O += P V
#pragma unroll 8
        for (int k = 0; k < 64; k++) {
            float p[4], v[4];
            *(float4*)p = *(const float4*)&PsT[k*AT_STRIDE + ty*4];
            *(float4*)v = *(const float4*)&Vs [k*AT_STRIDE + tx*4];
#pragma unroll
            for (int i = 0; i < 4; i++)
#pragma unroll
                for (int j = 0; j < 4; j++)
                    o[i][j] = fmaf(p[i], v[j], o[i][j]);
        }
    }

    // epilogue
#pragma unroll
    for (int i = 0; i < 4; i++) {
        float inv = 1.0f / l[i];
        float4 v = make_float4(o[i][0]*inv, o[i][1]*inv, o[i][2]*inv, o[i][3]*inv);
        *(float4*)&g_O[(size_t)(b*TLEN + q0 + ty*4 + i)*DDIM + h*DH + tx*4] = v;
    }
}

// ============================================================
// host launcher
// ============================================================
extern "C" void kernel_launch(void* const* d_in, const int* in_sizes, int n_in,
                              void* d_out, int out_size)
{
    const float* x_q = (const float*)d_in[0];
    const float* x_k = (const float*)d_in[1];
    const float* x_v = (const float*)d_in[2];
    const unsigned char* mask_raw = (const unsigned char*)d_in[3];
    const float* Wq = (const float*)d_in[4];
    const float* Wk = (const float*)d_in[5];
    const float* Wv = (const float*)d_in[6];
    const float* Wo = (const float*)d_in[7];
    const float* pos_emb = (const float*)d_in[8];
    float* out = (float*)d_out;

    void* p;
    cudaGetSymbolAddress(&p, g_Q);  float* Qb = (float*)p;
    cudaGetSymbolAddress(&p, g_K);  float* Kb = (float*)p;
    cudaGetSymbolAddress(&p, g_V);  float* Vb = (float*)p;
    cudaGetSymbolAddress(&p, g_O);  float* Ob = (float*)p;

    cudaFuncSetAttribute(qp_kernel,   cudaFuncAttributeMaxDynamicSharedMemorySize, QP_SMEM);
    cudaFuncSetAttribute(attn_kernel, cudaFuncAttributeMaxDynamicSharedMemorySize, AT_SMEM);

    const int M = BSZ*TLEN, N = DDIM, K = DDIM;
    dim3 gg(N/128, M/128);

    mask_prep<<<1, 256>>>(mask_raw);

    sgemm_nt<<<gg, 256>>>(x_q, Wq, Qb, M, N, K);
    sgemm_nt<<<gg, 256>>>(x_k, Wk, Kb, M, N, K);
    sgemm_nt<<<gg, 256>>>(x_v, Wv, Vb, M, N, K);

    qp_kernel<<<BSZ*NH*(TLEN/64), 256, QP_SMEM>>>(pos_emb);
    attn_kernel<<<BSZ*NH*(TLEN/64), 256, AT_SMEM>>>();

    sgemm_nt<<<gg, 256>>>(Ob, Wo, out, M, N, K);
}

// round 9
// speedup vs baseline: 1.4958x; 1.4958x over previous
#include <cuda_runtime.h>
#include <cuda_bf16.h>
#include <math.h>
#include <stdint.h>

// Problem constants
#define BSZ   4
#define TLEN  1024
#define DDIM  1024
#define NH    16
#define DH    64
#define LPOS  128
#define NPOS  257            // 2*L+1
#define QPS   272            // padded stride for Qp rows
#define INV_SCALE 0.125f     // 1/sqrt(D/H) = 1/8

// -------- device scratch (no allocations allowed) --------
__device__ float g_Q [BSZ*TLEN*DDIM];
__device__ float g_K [BSZ*TLEN*DDIM];
__device__ float g_V [BSZ*TLEN*DDIM];
__device__ float g_O [BSZ*TLEN*DDIM];
__device__ float g_Qp[BSZ*NH*TLEN*QPS];
__device__ unsigned char g_mask[BSZ*TLEN];
// bf16 split buffers (reused across the 4 GEMMs, which run sequentially)
__device__ __nv_bfloat16 g_Ahi[BSZ*TLEN*DDIM];
__device__ __nv_bfloat16 g_Alo[BSZ*TLEN*DDIM];
__device__ __nv_bfloat16 g_Bhi[DDIM*DDIM];
__device__ __nv_bfloat16 g_Blo[DDIM*DDIM];

// ============================================================
// mask_prep: normalize mask (int32-widened bool OR byte bool) to uint8
// ============================================================
__global__ void mask_prep(const unsigned char* __restrict__ mraw)
{
    __shared__ int s_bytefmt;
    if (threadIdx.x == 0) s_bytefmt = 0;
    __syncthreads();

    int local = 0;
    for (int i = threadIdx.x; i < BSZ*TLEN; i += blockDim.x)
        if ((i & 3) != 0 && mraw[i] != 0) local = 1;
    if (local) atomicOr(&s_bytefmt, 1);
    __syncthreads();

    if (s_bytefmt) {
        for (int i = threadIdx.x; i < BSZ*TLEN; i += blockDim.x)
            g_mask[i] = mraw[i] ? 1 : 0;
    } else {
        const int* mi = (const int*)mraw;
        for (int i = threadIdx.x; i < BSZ*TLEN; i += blockDim.x)
            g_mask[i] = mi[i] ? 1 : 0;
    }
}

// ============================================================
// split_bf16: x(fp32) -> hi(bf16) + lo(bf16), vectorized by 4
// ============================================================
__global__ void __launch_bounds__(256) split_bf16(
    const float* __restrict__ x, __nv_bfloat16* __restrict__ hi,
    __nv_bfloat16* __restrict__ lo, int n4)
{
    int i = blockIdx.x * blockDim.x + threadIdx.x;
    if (i >= n4) return;
    float4 v = ((const float4*)x)[i];
    __nv_bfloat16 h0 = __float2bfloat16(v.x);
    __nv_bfloat16 h1 = __float2bfloat16(v.y);
    __nv_bfloat16 h2 = __float2bfloat16(v.z);
    __nv_bfloat16 h3 = __float2bfloat16(v.w);
    __nv_bfloat16 l0 = __float2bfloat16(v.x - __bfloat162float(h0));
    __nv_bfloat16 l1 = __float2bfloat16(v.y - __bfloat162float(h1));
    __nv_bfloat16 l2 = __float2bfloat16(v.z - __bfloat162float(h2));
    __nv_bfloat16 l3 = __float2bfloat16(v.w - __bfloat162float(h3));
    __nv_bfloat162 hp0; hp0.x = h0; hp0.y = h1;
    __nv_bfloat162 hp1; hp1.x = h2; hp1.y = h3;
    __nv_bfloat162 lp0; lp0.x = l0; lp0.y = l1;
    __nv_bfloat162 lp1; lp1.x = l2; lp1.y = l3;
    ((__nv_bfloat162*)hi)[2*i]     = hp0;
    ((__nv_bfloat162*)hi)[2*i + 1] = hp1;
    ((__nv_bfloat162*)lo)[2*i]     = lp0;
    ((__nv_bfloat162*)lo)[2*i + 1] = lp1;
}

// ============================================================
// mma.sync helpers (base sm_103 features: HMMA + ldmatrix + cp.async)
// ============================================================
#define LDMX4(r0, r1, r2, r3, addr) \
    asm volatile("ldmatrix.sync.aligned.m8n8.x4.shared.b16 {%0,%1,%2,%3}, [%4];" \
        : "=r"(r0), "=r"(r1), "=r"(r2), "=r"(r3) : "r"(addr))

#define MMA16816(c, a, b) \
    asm volatile("mma.sync.aligned.m16n8k16.row.col.f32.bf16.bf16.f32 " \
        "{%0,%1,%2,%3}, {%4,%5,%6,%7}, {%8,%9}, {%0,%1,%2,%3};" \
        : "+f"((c)[0]), "+f"((c)[1]), "+f"((c)[2]), "+f"((c)[3]) \
        : "r"((a)[0]), "r"((a)[1]), "r"((a)[2]), "r"((a)[3]), \
          "r"((b)[0]), "r"((b)[1]))

// ============================================================
// Tensor-core split-bf16 GEMM NT via mma.sync:
//   C[M,N] = (Ahi+Alo)[M,K] * (Bhi+Blo)[N,K]^T   (hi*hi + hi*lo + lo*hi)
// 128x128 tile/CTA, BK=32, 8 warps (4m x 2n), warp tile 32x64.
// Smem row stride 40 bf16 (80B) -> conflict-free ldmatrix.
// ============================================================
#define GEMM_BK      32
#define T_STRIDE     40                 // bf16 elems per smem row
#define T_BYTES      (128*T_STRIDE*2)   // 10240 per tile
#define BUF_BYTES    (4*T_BYTES)        // Ahi,Alo,Bhi,Blo
#define GM_SMEM      (2*BUF_BYTES)      // 81920

__device__ __forceinline__ void gm_load_chunk(
    uint32_t sbuf,
    const __nv_bfloat16* __restrict__ Ahi, const __nv_bfloat16* __restrict__ Alo,
    const __nv_bfloat16* __restrict__ Bhi, const __nv_bfloat16* __restrict__ Blo,
    int m0, int n0, int k0, int tid)
{
#pragma unroll
    for (int j = 0; j < 8; j++) {
        int i = tid + j * 256;
        int t = i >> 9, idx = i & 511, row = idx >> 2, seg = idx & 3;
        uint32_t dst = sbuf + t * T_BYTES + row * (T_STRIDE*2) + seg * 16;
        const __nv_bfloat16* s = (t == 0) ? Ahi : (t == 1) ? Alo : (t == 2) ? Bhi : Blo;
        int gr = ((t < 2) ? m0 : n0) + row;
        const void* src = s + (size_t)gr * DDIM + k0 + seg * 8;
        asm volatile("cp.async.cg.shared.global [%0], [%1], 16;"
                     :: "r"(dst), "l"(src) : "memory");
    }
    asm volatile("cp.async.commit_group;" ::: "memory");
}

__global__ void __launch_bounds__(256, 1) gemm_mma(
    const __nv_bfloat16* __restrict__ Ahi, const __nv_bfloat16* __restrict__ Alo,
    const __nv_bfloat16* __restrict__ Bhi, const __nv_bfloat16* __restrict__ Blo,
    float* __restrict__ C)
{
    extern __shared__ __align__(128) char smc[];
    const uint32_t smb = (uint32_t)__cvta_generic_to_shared(smc);
    const int tid = threadIdx.x, lane = tid & 31, wid = tid >> 5;
    const int wm = wid & 3, wn = wid >> 1 & 4 ? 0 : 0;  // placeholder, fixed below
    const int warp_n = wid >> 2;                        // 0..1
    const int m0 = blockIdx.y * 128, n0 = blockIdx.x * 128;

    float acc[2][8][4];
#pragma unroll
    for (int mi = 0; mi < 2; mi++)
#pragma unroll
        for (int ni = 0; ni < 8; ni++)
#pragma unroll
            for (int r = 0; r < 4; r++) acc[mi][ni][r] = 0.0f;

    // per-lane ldmatrix row/col (element units within a tile)
    const int sel = lane >> 3, rowl = lane & 7;
    const int arow = wm * 32 + rowl + (sel & 1) * 8;
    const int acol = (sel >> 1) * 8;
    const int brow = warp_n * 64 + rowl + (sel >> 1) * 8;
    const int bcol = (sel & 1) * 8;

    gm_load_chunk(smb, Ahi, Alo, Bhi, Blo, m0, n0, 0, tid);

    const int NCH = DDIM / GEMM_BK;   // 32
    for (int ch = 0; ch < NCH; ch++) {
        asm volatile("cp.async.wait_group 0;" ::: "memory");
        __syncthreads();
        if (ch + 1 < NCH)
            gm_load_chunk(smb + ((ch + 1) & 1) * BUF_BYTES,
                          Ahi, Alo, Bhi, Blo, m0, n0, (ch + 1) * GEMM_BK, tid);
        const uint32_t tb = smb + (ch & 1) * BUF_BYTES;
#pragma unroll
        for (int ks = 0; ks < 2; ks++) {
            uint32_t ah[2][4], al[2][4], bh[8][2], bl[8][2];
#pragma unroll
            for (int mi = 0; mi < 2; mi++) {
                uint32_t off = ((arow + mi * 16) * T_STRIDE + acol + ks * 16) * 2;
                LDMX4(ah[mi][0], ah[mi][1], ah[mi][2], ah[mi][3], tb + off);
                LDMX4(al[mi][0], al[mi][1], al[mi][2], al[mi][3], tb + T_BYTES + off);
            }
#pragma unroll
            for (int p = 0; p < 4; p++) {
                uint32_t off = ((brow + p * 16) * T_STRIDE + bcol + ks * 16) * 2;
                LDMX4(bh[2*p][0], bh[2*p][1], bh[2*p+1][0], bh[2*p+1][1],
                      tb + 2 * T_BYTES + off);
                LDMX4(bl[2*p][0], bl[2*p][1], bl[2*p+1][0], bl[2*p+1][1],
                      tb + 3 * T_BYTES + off);
            }
#pragma unroll
            for (int mi = 0; mi < 2; mi++)
#pragma unroll
                for (int ni = 0; ni < 8; ni++) {
                    MMA16816(acc[mi][ni], ah[mi], bh[ni]);
                    MMA16816(acc[mi][ni], ah[mi], bl[ni]);
                    MMA16816(acc[mi][ni], al[mi], bh[ni]);
                }
        }
    }

    // epilogue
    const int g = lane >> 2, t4 = lane & 3;
#pragma unroll
    for (int mi = 0; mi < 2; mi++) {
        const int r = m0 + wm * 32 + mi * 16 + g;
#pragma unroll
        for (int ni = 0; ni < 8; ni++) {
            const int col = n0 + warp_n * 64 + ni * 8 + t4 * 2;
            *(float2*)&C[(size_t)r * DDIM + col] =
                make_float2(acc[mi][ni][0], acc[mi][ni][1]);
            *(float2*)&C[(size_t)(r + 8) * DDIM + col] =
                make_float2(acc[mi][ni][2], acc[mi][ni][3]);
        }
    }
    (void)wn;
}

// ============================================================
// Qp[b,h,q,r] = sum_d Q[b,q,h*DH+d] * pos_emb[r,d]
// ============================================================
#define QP_SMEM ((64*64 + NPOS*65) * 4)
__global__ void __launch_bounds__(256) qp_kernel(const float* __restrict__ pos_emb)
{
    extern __shared__ float sm[];
    float* Qs = sm;              // [q][d] stride 64
    float* Ps = sm + 64*64;      // [r][d] stride 65

    const int blk = blockIdx.x;
    const int qt = blk & 15, h = (blk >> 4) & 15, b = blk >> 8;
    const int q0 = qt * 64;
    const int tid = threadIdx.x;

    for (int i = tid; i < 64*64; i += 256) {
        int q = i >> 6, d = i & 63;
        Qs[q*64 + d] = g_Q[(size_t)(b*TLEN + q0 + q)*DDIM + h*DH + d];
    }
    for (int i = tid; i < NPOS*DH; i += 256) {
        int r = i >> 6, d = i & 63;
        Ps[r*65 + d] = pos_emb[i];
    }
    __syncthreads();

    const int rowbase = (b*NH + h)*TLEN + q0;
    for (int idx = tid; idx < 64*NPOS; idx += 256) {
        int q = idx / NPOS;
        int r = idx - q*NPOS;
        const float* qr = Qs + q*64;
        const float* pr = Ps + r*65;
        float s = 0.0f;
#pragma unroll 16
        for (int d = 0; d < 64; d++) s = fmaf(qr[d], pr[d], s);
        g_Qp[(size_t)(rowbase + q)*QPS + r] = s;
    }
}

// ============================================================
// Flash-style attention (fp32 SIMT) — unchanged
// ============================================================
#define AT_STRIDE 68
#define AT_SMEM (4 * 64 * AT_STRIDE * 4)
__global__ void __launch_bounds__(256) attn_kernel()
{
    extern __shared__ float sm[];
    float* QsT = sm;                     // [d][q]
    float* KsT = QsT + 64*AT_STRIDE;     // [d][k]
    float* Vs  = KsT + 64*AT_STRIDE;     // [k][d]
    float* PsT = Vs  + 64*AT_STRIDE;     // [k][q]

    const int blk = blockIdx.x;
    const int qt = blk & 15, h = (blk >> 4) & 15, b = blk >> 8;
    const int q0 = qt * 64;
    const int tid = threadIdx.x;
    const int tx = tid & 15, ty = tid >> 4;

    for (int i = tid; i < 64*64; i += 256) {
        int q = i >> 6, d = i & 63;
        QsT[d*AT_STRIDE + q] = g_Q[(size_t)(b*TLEN + q0 + q)*DDIM + h*DH + d];
    }

    float m[4], l[4], o[4][4];
#pragma unroll
    for (int i = 0; i < 4; i++) {
        m[i] = -1e30f; l[i] = 0.0f;
#pragma unroll
        for (int j = 0; j < 4; j++) o[i][j] = 0.0f;
    }

    const int qp_rowbase = (b*NH + h)*TLEN + q0;

    for (int kt = 0; kt < 16; kt++) {
        const int k0 = kt * 64;
        __syncthreads();
        for (int i = tid; i < 64*64; i += 256) {
            int k = i >> 6, d = i & 63;
            size_t gidx = (size_t)(b*TLEN + k0 + k)*DDIM + h*DH + d;
            KsT[d*AT_STRIDE + k] = g_K[gidx];
            Vs [k*AT_STRIDE + d] = g_V[gidx];
        }
        __syncthreads();

        float s[4][4];
#pragma unroll
        for (int i = 0; i < 4; i++)
#pragma unroll
            for (int j = 0; j < 4; j++) s[i][j] = 0.0f;
#pragma unroll 8
        for (int d = 0; d < 64; d++) {
            float a[4], bb[4];
            *(float4*)a  = *(const float4*)&QsT[d*AT_STRIDE + ty*4];
            *(float4*)bb = *(const float4*)&KsT[d*AT_STRIDE + tx*4];
#pragma unroll
            for (int i = 0; i < 4; i++)
#pragma unroll
                for (int j = 0; j < 4; j++)
                    s[i][j] = fmaf(a[i], bb[j], s[i][j]);
        }

        unsigned char mk[4];
#pragma unroll
        for (int j = 0; j < 4; j++) mk[j] = g_mask[b*TLEN + k0 + tx*4 + j];

#pragma unroll
        for (int i = 0; i < 4; i++) {
            const int q = q0 + ty*4 + i;
            const float* qpr = g_Qp + (size_t)(qp_rowbase + ty*4 + i)*QPS;
#pragma unroll
            for (int j = 0; j < 4; j++) {
                int k = k0 + tx*4 + j;
                int r = k - q;
                r = r < -LPOS ? -LPOS : (r > LPOS ? LPOS : r);
                float v = (s[i][j] + qpr[r + LPOS]) * INV_SCALE;
                s[i][j] = mk[j] ? -1e30f : v;
            }
        }

#pragma unroll
        for (int i = 0; i < 4; i++) {
            float rm = s[i][0];
#pragma unroll
            for (int j = 1; j < 4; j++) rm = fmaxf(rm, s[i][j]);
            rm = fmaxf(rm, __shfl_xor_sync(0xffffffffu, rm, 8));
            rm = fmaxf(rm, __shfl_xor_sync(0xffffffffu, rm, 4));
            rm = fmaxf(rm, __shfl_xor_sync(0xffffffffu, rm, 2));
            rm = fmaxf(rm, __shfl_xor_sync(0xffffffffu, rm, 1));
            float mnew = fmaxf(m[i], rm);
            float alpha = __expf(m[i] - mnew);
            float p[4], rs = 0.0f;
#pragma unroll
            for (int j = 0; j < 4; j++) { p[j] = __expf(s[i][j] - mnew); rs += p[j]; }
            rs += __shfl_xor_sync(0xffffffffu, rs, 8);
            rs += __shfl_xor_sync(0xffffffffu, rs, 4);
            rs += __shfl_xor_sync(0xffffffffu, rs, 2);
            rs += __shfl_xor_sync(0xffffffffu, rs, 1);
            l[i] = l[i]*alpha + rs;
            m[i] = mnew;
#pragma unroll
            for (int j = 0; j < 4; j++) PsT[(tx*4 + j)*AT_STRIDE + ty*4 + i] = p[j];
#pragma unroll
            for (int j = 0; j < 4; j++) o[i][j] *= alpha;
        }
        __syncthreads();

#pragma unroll 8
        for (int k = 0; k < 64; k++) {
            float p[4], v[4];
            *(float4*)p = *(const float4*)&PsT[k*AT_STRIDE + ty*4];
            *(float4*)v = *(const float4*)&Vs [k*AT_STRIDE + tx*4];
#pragma unroll
            for (int i = 0; i < 4; i++)
#pragma unroll
                for (int j = 0; j < 4; j++)
                    o[i][j] = fmaf(p[i], v[j], o[i][j]);
        }
    }

#pragma unroll
    for (int i = 0; i < 4; i++) {
        float inv = 1.0f / l[i];
        float4 v = make_float4(o[i][0]*inv, o[i][1]*inv, o[i][2]*inv, o[i][3]*inv);
        *(float4*)&g_O[(size_t)(b*TLEN + q0 + ty*4 + i)*DDIM + h*DH + tx*4] = v;
    }
}

// ============================================================
// host launcher
// ============================================================
extern "C" void kernel_launch(void* const* d_in, const int* in_sizes, int n_in,
                              void* d_out, int out_size)
{
    const float* x_q = (const float*)d_in[0];
    const float* x_k = (const float*)d_in[1];
    const float* x_v = (const float*)d_in[2];
    const unsigned char* mask_raw = (const unsigned char*)d_in[3];
    const float* Wq = (const float*)d_in[4];
    const float* Wk = (const float*)d_in[5];
    const float* Wv = (const float*)d_in[6];
    const float* Wo = (const float*)d_in[7];
    const float* pos_emb = (const float*)d_in[8];
    float* out = (float*)d_out;

    void* p;
    cudaGetSymbolAddress(&p, g_Q);   float* Qb  = (float*)p;
    cudaGetSymbolAddress(&p, g_K);   float* Kb  = (float*)p;
    cudaGetSymbolAddress(&p, g_V);   float* Vb  = (float*)p;
    cudaGetSymbolAddress(&p, g_O);   float* Ob  = (float*)p;
    cudaGetSymbolAddress(&p, g_Ahi); __nv_bfloat16* Ahi = (__nv_bfloat16*)p;
    cudaGetSymbolAddress(&p, g_Alo); __nv_bfloat16* Alo = (__nv_bfloat16*)p;
    cudaGetSymbolAddress(&p, g_Bhi); __nv_bfloat16* Bhi = (__nv_bfloat16*)p;
    cudaGetSymbolAddress(&p, g_Blo); __nv_bfloat16* Blo = (__nv_bfloat16*)p;

    cudaFuncSetAttribute(qp_kernel,   cudaFuncAttributeMaxDynamicSharedMemorySize, QP_SMEM);
    cudaFuncSetAttribute(attn_kernel, cudaFuncAttributeMaxDynamicSharedMemorySize, AT_SMEM);
    cudaFuncSetAttribute(gemm_mma,    cudaFuncAttributeMaxDynamicSharedMemorySize, GM_SMEM);

    const int M = BSZ*TLEN, N = DDIM;
    const int n4A = (BSZ*TLEN*DDIM) / 4;   // 1,048,576
    const int n4W = (DDIM*DDIM) / 4;       // 262,144
    dim3 gt(N/128, M/128);                 // (8, 32)

    mask_prep<<<1, 256>>>(mask_raw);

    // Q = x_q @ Wq^T
    split_bf16<<<n4A/256, 256>>>(x_q, Ahi, Alo, n4A);
    split_bf16<<<n4W/256, 256>>>(Wq,  Bhi, Blo, n4W);
    gemm_mma<<<gt, 256, GM_SMEM>>>(Ahi, Alo, Bhi, Blo, Qb);

    // K = x_k @ Wk^T
    split_bf16<<<n4A/256, 256>>>(x_k, Ahi, Alo, n4A);
    split_bf16<<<n4W/256, 256>>>(Wk,  Bhi, Blo, n4W);
    gemm_mma<<<gt, 256, GM_SMEM>>>(Ahi, Alo, Bhi, Blo, Kb);

    // V = x_v @ Wv^T
    split_bf16<<<n4A/256, 256>>>(x_v, Ahi, Alo, n4A);
    split_bf16<<<n4W/256, 256>>>(Wv,  Bhi, Blo, n4W);
    gemm_mma<<<gt, 256, GM_SMEM>>>(Ahi, Alo, Bhi, Blo, Vb);

    qp_kernel<<<BSZ*NH*(TLEN/64), 256, QP_SMEM>>>(pos_emb);
    attn_kernel<<<BSZ*NH*(TLEN/64), 256, AT_SMEM>>>();

    // out = O @ Wo^T
    split_bf16<<<n4A/256, 256>>>(Ob, Ahi, Alo, n4A);
    split_bf16<<<n4W/256, 256>>>(Wo, Bhi, Blo, n4W);
    gemm_mma<<<gt, 256, GM_SMEM>>>(Ahi, Alo, Bhi, Blo, out);
}

// round 12
// speedup vs baseline: 1.8592x; 1.2430x over previous
#include <cuda_runtime.h>
#include <cuda_bf16.h>
#include <math.h>
#include <stdint.h>

// Problem constants
#define BSZ   4
#define TLEN  1024
#define DDIM  1024
#define NH    16
#define DH    64
#define LPOS  128
#define NPOS  257            // 2*L+1
#define QPS   272            // padded stride for Qp rows
#define INV_SCALE 0.125f     // 1/sqrt(D/H) = 1/8

// -------- device scratch (no allocations allowed) --------
__device__ float g_Q [BSZ*TLEN*DDIM];          // fp32 Q (for qp_kernel)
__device__ float g_Qp[BSZ*NH*TLEN*QPS];
__device__ float g_maskbias[BSZ*TLEN];         // 0 or -1e30
// bf16 split buffers
__device__ __nv_bfloat16 g_Ahi[BSZ*TLEN*DDIM];
__device__ __nv_bfloat16 g_Alo[BSZ*TLEN*DDIM];
__device__ __nv_bfloat16 g_Bhi[DDIM*DDIM];
__device__ __nv_bfloat16 g_Blo[DDIM*DDIM];
__device__ __nv_bfloat16 g_Qhi[BSZ*TLEN*DDIM];
__device__ __nv_bfloat16 g_Qlo[BSZ*TLEN*DDIM];
__device__ __nv_bfloat16 g_Khi[BSZ*TLEN*DDIM];
__device__ __nv_bfloat16 g_Klo[BSZ*TLEN*DDIM];
__device__ __nv_bfloat16 g_Vhi[BSZ*TLEN*DDIM];
__device__ __nv_bfloat16 g_Vlo[BSZ*TLEN*DDIM];

// ============================================================
// small helpers
// ============================================================
__device__ __forceinline__ uint32_t pack_bf16(float lo, float hi) {
    uint32_t d;
    asm("cvt.rn.bf16x2.f32 %0, %1, %2;" : "=r"(d) : "f"(hi), "f"(lo));
    return d;
}
__device__ __forceinline__ float bf16lo_f(uint32_t u) { return __uint_as_float(u << 16); }
__device__ __forceinline__ float bf16hi_f(uint32_t u) { return __uint_as_float(u & 0xffff0000u); }

// ============================================================
// mask_prep: normalize mask (int32-widened bool OR byte bool) -> float bias
// ============================================================
__global__ void mask_prep(const unsigned char* __restrict__ mraw)
{
    __shared__ int s_bytefmt;
    if (threadIdx.x == 0) s_bytefmt = 0;
    __syncthreads();

    int local = 0;
    for (int i = threadIdx.x; i < BSZ*TLEN; i += blockDim.x)
        if ((i & 3) != 0 && mraw[i] != 0) local = 1;
    if (local) atomicOr(&s_bytefmt, 1);
    __syncthreads();

    if (s_bytefmt) {
        for (int i = threadIdx.x; i < BSZ*TLEN; i += blockDim.x)
            g_maskbias[i] = mraw[i] ? -1e30f : 0.0f;
    } else {
        const int* mi = (const int*)mraw;
        for (int i = threadIdx.x; i < BSZ*TLEN; i += blockDim.x)
            g_maskbias[i] = mi[i] ? -1e30f : 0.0f;
    }
}

// ============================================================
// split_bf16: x(fp32) -> hi(bf16) + lo(bf16), vectorized by 4
// ============================================================
__global__ void __launch_bounds__(256) split_bf16(
    const float* __restrict__ x, __nv_bfloat16* __restrict__ hi,
    __nv_bfloat16* __restrict__ lo, int n4)
{
    int i = blockIdx.x * blockDim.x + threadIdx.x;
    if (i >= n4) return;
    float4 v = ((const float4*)x)[i];
    uint32_t h0 = pack_bf16(v.x, v.y);
    uint32_t h1 = pack_bf16(v.z, v.w);
    uint32_t l0 = pack_bf16(v.x - bf16lo_f(h0), v.y - bf16hi_f(h0));
    uint32_t l1 = pack_bf16(v.z - bf16lo_f(h1), v.w - bf16hi_f(h1));
    ((uint2*)hi)[i] = make_uint2(h0, h1);
    ((uint2*)lo)[i] = make_uint2(l0, l1);
}

// ============================================================
// mma.sync helpers (base sm_103 features)
// ============================================================
#define LDMX4(r0, r1, r2, r3, addr) \
    asm volatile("ldmatrix.sync.aligned.m8n8.x4.shared.b16 {%0,%1,%2,%3}, [%4];" \
        : "=r"(r0), "=r"(r1), "=r"(r2), "=r"(r3) : "r"(addr))

#define LDMX4T(r0, r1, r2, r3, addr) \
    asm volatile("ldmatrix.sync.aligned.m8n8.x4.trans.shared.b16 {%0,%1,%2,%3}, [%4];" \
        : "=r"(r0), "=r"(r1), "=r"(r2), "=r"(r3) : "r"(addr))

#define MMA16816(c, a, b) \
    asm volatile("mma.sync.aligned.m16n8k16.row.col.f32.bf16.bf16.f32 " \
        "{%0,%1,%2,%3}, {%4,%5,%6,%7}, {%8,%9}, {%0,%1,%2,%3};" \
        : "+f"((c)[0]), "+f"((c)[1]), "+f"((c)[2]), "+f"((c)[3]) \
        : "r"((a)[0]), "r"((a)[1]), "r"((a)[2]), "r"((a)[3]), \
          "r"((b)[0]), "r"((b)[1]))

// ============================================================
// Tensor-core split-bf16 GEMM NT via mma.sync:
//   out = (Ahi+Alo)[M,K] * (Bhi+Blo)[N,K]^T   (hi*hi + hi*lo + lo*hi)
// Optional fp32 C and optional bf16 hi/lo split outputs.
// ============================================================
#define GEMM_BK      32
#define T_STRIDE     40
#define T_BYTES      (128*T_STRIDE*2)
#define BUF_BYTES    (4*T_BYTES)
#define GM_SMEM      (2*BUF_BYTES)

__device__ __forceinline__ void gm_load_chunk(
    uint32_t sbuf,
    const __nv_bfloat16* __restrict__ Ahi, const __nv_bfloat16* __restrict__ Alo,
    const __nv_bfloat16* __restrict__ Bhi, const __nv_bfloat16* __restrict__ Blo,
    int m0, int n0, int k0, int tid)
{
#pragma unroll
    for (int j = 0; j < 8; j++) {
        int i = tid + j * 256;
        int t = i >> 9, idx = i & 511, row = idx >> 2, seg = idx & 3;
        uint32_t dst = sbuf + t * T_BYTES + row * (T_STRIDE*2) + seg * 16;
        const __nv_bfloat16* s = (t == 0) ? Ahi : (t == 1) ? Alo : (t == 2) ? Bhi : Blo;
        int gr = ((t < 2) ? m0 : n0) + row;
        const void* src = s + (size_t)gr * DDIM + k0 + seg * 8;
        asm volatile("cp.async.cg.shared.global [%0], [%1], 16;"
                     :: "r"(dst), "l"(src) : "memory");
    }
    asm volatile("cp.async.commit_group;" ::: "memory");
}

__global__ void __launch_bounds__(256, 1) gemm_mma(
    const __nv_bfloat16* __restrict__ Ahi, const __nv_bfloat16* __restrict__ Alo,
    const __nv_bfloat16* __restrict__ Bhi, const __nv_bfloat16* __restrict__ Blo,
    float* __restrict__ C,
    __nv_bfloat16* __restrict__ Chi, __nv_bfloat16* __restrict__ Clo)
{
    extern __shared__ __align__(128) char smc[];
    const uint32_t smb = (uint32_t)__cvta_generic_to_shared(smc);
    const int tid = threadIdx.x, lane = tid & 31, wid = tid >> 5;
    const int wm = wid & 3;
    const int warp_n = wid >> 2;
    const int m0 = blockIdx.y * 128, n0 = blockIdx.x * 128;

    float acc[2][8][4];
#pragma unroll
    for (int mi = 0; mi < 2; mi++)
#pragma unroll
        for (int ni = 0; ni < 8; ni++)
#pragma unroll
            for (int r = 0; r < 4; r++) acc[mi][ni][r] = 0.0f;

    const int sel = lane >> 3, rowl = lane & 7;
    const int arow = wm * 32 + rowl + (sel & 1) * 8;
    const int acol = (sel >> 1) * 8;
    const int brow = warp_n * 64 + rowl + (sel >> 1) * 8;
    const int bcol = (sel & 1) * 8;

    gm_load_chunk(smb, Ahi, Alo, Bhi, Blo, m0, n0, 0, tid);

    const int NCH = DDIM / GEMM_BK;
    for (int ch = 0; ch < NCH; ch++) {
        asm volatile("cp.async.wait_group 0;" ::: "memory");
        __syncthreads();
        if (ch + 1 < NCH)
            gm_load_chunk(smb + ((ch + 1) & 1) * BUF_BYTES,
                          Ahi, Alo, Bhi, Blo, m0, n0, (ch + 1) * GEMM_BK, tid);
        const uint32_t tb = smb + (ch & 1) * BUF_BYTES;
#pragma unroll
        for (int ks = 0; ks < 2; ks++) {
            uint32_t ah[2][4], al[2][4], bh[8][2], bl[8][2];
#pragma unroll
            for (int mi = 0; mi < 2; mi++) {
                uint32_t off = ((arow + mi * 16) * T_STRIDE + acol + ks * 16) * 2;
                LDMX4(ah[mi][0], ah[mi][1], ah[mi][2], ah[mi][3], tb + off);
                LDMX4(al[mi][0], al[mi][1], al[mi][2], al[mi][3], tb + T_BYTES + off);
            }
#pragma unroll
            for (int p = 0; p < 4; p++) {
                uint32_t off = ((brow + p * 16) * T_STRIDE + bcol + ks * 16) * 2;
                LDMX4(bh[2*p][0], bh[2*p][1], bh[2*p+1][0], bh[2*p+1][1],
                      tb + 2 * T_BYTES + off);
                LDMX4(bl[2*p][0], bl[2*p][1], bl[2*p+1][0], bl[2*p+1][1],
                      tb + 3 * T_BYTES + off);
            }
#pragma unroll
            for (int mi = 0; mi < 2; mi++)
#pragma unroll
                for (int ni = 0; ni < 8; ni++) {
                    MMA16816(acc[mi][ni], ah[mi], bh[ni]);
                    MMA16816(acc[mi][ni], ah[mi], bl[ni]);
                    MMA16816(acc[mi][ni], al[mi], bh[ni]);
                }
        }
    }

    // epilogue: fp32 (optional) + bf16 hi/lo split (optional)
    const int g = lane >> 2, t4 = lane & 3;
#pragma unroll
    for (int mi = 0; mi < 2; mi++) {
        const int r = m0 + wm * 32 + mi * 16 + g;
#pragma unroll
        for (int ni = 0; ni < 8; ni++) {
            const int col = n0 + warp_n * 64 + ni * 8 + t4 * 2;
            const size_t i0 = (size_t)r * DDIM + col;
            const size_t i1 = (size_t)(r + 8) * DDIM + col;
            float v0 = acc[mi][ni][0], v1 = acc[mi][ni][1];
            float v2 = acc[mi][ni][2], v3 = acc[mi][ni][3];
            if (C) {
                *(float2*)&C[i0] = make_float2(v0, v1);
                *(float2*)&C[i1] = make_float2(v2, v3);
            }
            if (Chi) {
                uint32_t h0 = pack_bf16(v0, v1);
                uint32_t h1 = pack_bf16(v2, v3);
                *(uint32_t*)(Chi + i0) = h0;
                *(uint32_t*)(Chi + i1) = h1;
                *(uint32_t*)(Clo + i0) =
                    pack_bf16(v0 - bf16lo_f(h0), v1 - bf16hi_f(h0));
                *(uint32_t*)(Clo + i1) =
                    pack_bf16(v2 - bf16lo_f(h1), v3 - bf16hi_f(h1));
            }
        }
    }
}

// ============================================================
// Qp[b,h,q,r] = sum_d Q[b,q,h*DH+d] * pos_emb[r,d]
// ============================================================
#define QP_SMEM ((64*64 + NPOS*65) * 4)
__global__ void __launch_bounds__(256) qp_kernel(const float* __restrict__ pos_emb)
{
    extern __shared__ float sm[];
    float* Qs = sm;              // [q][d] stride 64
    float* Ps = sm + 64*64;      // [r][d] stride 65

    const int blk = blockIdx.x;
    const int qt = blk & 15, h = (blk >> 4) & 15, b = blk >> 8;
    const int q0 = qt * 64;
    const int tid = threadIdx.x;

    for (int i = tid; i < 64*64; i += 256) {
        int q = i >> 6, d = i & 63;
        Qs[q*64 + d] = g_Q[(size_t)(b*TLEN + q0 + q)*DDIM + h*DH + d];
    }
    for (int i = tid; i < NPOS*DH; i += 256) {
        int r = i >> 6, d = i & 63;
        Ps[r*65 + d] = pos_emb[i];
    }
    __syncthreads();

    const int rowbase = (b*NH + h)*TLEN + q0;
    for (int idx = tid; idx < 64*NPOS; idx += 256) {
        int q = idx / NPOS;
        int r = idx - q*NPOS;
        const float* qr = Qs + q*64;
        const float* pr = Ps + r*65;
        float s = 0.0f;
#pragma unroll 16
        for (int d = 0; d < 64; d++) s = fmaf(qr[d], pr[d], s);
        g_Qp[(size_t)(rowbase + q)*QPS + r] = s;
    }
}

// ============================================================
// Tensor-core flash attention:
//  - CTA: 128 q rows of one (b,h); 8 warps, each m16.
//  - S = Qh*Kh^T + Qh*Kl^T + Ql*Kh^T (fp32 accum in MMA frags)
//  - +pos gather, +mask bias, online softmax in fragment layout
//  - P split hi/lo in registers -> PV = Ph*Vh + Ph*Vl + Pl*Vh
//  - epilogue writes bf16 hi/lo straight into Wo-GEMM A-buffers
// ============================================================
#define KV_STRIDE 72
#define KV_TILE_B (64*KV_STRIDE*2)     // 9216
#define ATC_BUF   (4*KV_TILE_B)        // 36864
#define ATC_SMEM  (2*ATC_BUF)          // 73728
#define Q_TILE_B  (128*KV_STRIDE*2)    // 18432

__device__ __forceinline__ void at_load_kv(uint32_t sbuf,
    const __nv_bfloat16* __restrict__ Kh, const __nv_bfloat16* __restrict__ Kl,
    const __nv_bfloat16* __restrict__ Vh, const __nv_bfloat16* __restrict__ Vl,
    int bT, int hoff, int k0, int tid)
{
#pragma unroll
    for (int j = 0; j < 8; j++) {
        int i = tid + j * 256;
        int t = i >> 9, idx = i & 511, row = idx >> 3, seg = idx & 7;
        uint32_t dst = sbuf + t * KV_TILE_B + row * (KV_STRIDE*2) + seg * 16;
        const __nv_bfloat16* s = (t == 0) ? Kh : (t == 1) ? Kl : (t == 2) ? Vh : Vl;
        const void* src = s + (size_t)(bT + k0 + row) * DDIM + hoff + seg * 8;
        asm volatile("cp.async.cg.shared.global [%0], [%1], 16;"
                     :: "r"(dst), "l"(src) : "memory");
    }
    asm volatile("cp.async.commit_group;" ::: "memory");
}

__global__ void __launch_bounds__(256) attn_tc(
    __nv_bfloat16* __restrict__ Ohi, __nv_bfloat16* __restrict__ Olo)
{
    extern __shared__ __align__(128) char smc[];
    const uint32_t smb = (uint32_t)__cvta_generic_to_shared(smc);
    const int tid = threadIdx.x, lane = tid & 31, w = tid >> 5;
    const int qt = blockIdx.x & 7, h = (blockIdx.x >> 3) & 15, b = blockIdx.x >> 7;
    const int q0 = qt * 128, bT = b * TLEN, hoff = h * DH;

    const int rowl = lane & 7, sel = lane >> 3;
    const int arow = rowl + (sel & 1) * 8, acol = (sel >> 1) * 8;
    const int brow = rowl + (sel >> 1) * 8, bcol = (sel & 1) * 8;
    const int vrow = (sel & 1) * 8 + rowl, vcol = (sel >> 1) * 8;

    // stage Q hi/lo (128x64) into buf0
#pragma unroll
    for (int j = 0; j < 8; j++) {
        int i = tid + j * 256;
        int t = i >> 10, idx = i & 1023, row = idx >> 3, seg = idx & 7;
        uint32_t dst = smb + t * Q_TILE_B + row * (KV_STRIDE*2) + seg * 16;
        const __nv_bfloat16* s = t ? g_Qlo : g_Qhi;
        const void* src = s + (size_t)(bT + q0 + row) * DDIM + hoff + seg * 8;
        asm volatile("cp.async.cg.shared.global [%0], [%1], 16;"
                     :: "r"(dst), "l"(src) : "memory");
    }
    asm volatile("cp.async.commit_group;" ::: "memory");
    // prefetch KV tile 0 into buf1
    at_load_kv(smb + ATC_BUF, g_Khi, g_Klo, g_Vhi, g_Vlo, bT, hoff, 0, tid);

    asm volatile("cp.async.wait_group 1;" ::: "memory");
    __syncthreads();

    uint32_t qh[4][4], ql[4][4];
#pragma unroll
    for (int j = 0; j < 4; j++) {
        uint32_t off = ((w * 16 + arow) * KV_STRIDE + acol + j * 16) * 2;
        LDMX4(qh[j][0], qh[j][1], qh[j][2], qh[j][3], smb + off);
        LDMX4(ql[j][0], ql[j][1], ql[j][2], ql[j][3], smb + Q_TILE_B + off);
    }
    __syncthreads();   // buf0 now free for KV

    float o[8][4];
#pragma unroll
    for (int ni = 0; ni < 8; ni++)
#pragma unroll
        for (int r = 0; r < 4; r++) o[ni][r] = 0.0f;
    float mrow0 = -1e30f, mrow1 = -1e30f, lrow0 = 0.0f, lrow1 = 0.0f;

    const int qr0 = q0 + w * 16 + (lane >> 2);
    const float* qpr0 = g_Qp + ((size_t)(b*NH + h)*TLEN + qr0) * QPS;
    const float* qpr1 = qpr0 + 8 * QPS;
    const float* mb = g_maskbias + bT;

    for (int kt = 0; kt < 16; kt++) {
        const uint32_t vb = smb + ((kt & 1) ^ 1) * ATC_BUF;
        asm volatile("cp.async.wait_group 0;" ::: "memory");
        __syncthreads();
        if (kt + 1 < 16)
            at_load_kv(smb + (kt & 1) * ATC_BUF, g_Khi, g_Klo, g_Vhi, g_Vlo,
                       bT, hoff, (kt + 1) * 64, tid);

        // ---- S = Q K^T ----
        float s[8][4];
#pragma unroll
        for (int ni = 0; ni < 8; ni++)
#pragma unroll
            for (int r = 0; r < 4; r++) s[ni][r] = 0.0f;
#pragma unroll
        for (int j = 0; j < 4; j++) {
#pragma unroll
            for (int p = 0; p < 4; p++) {
                uint32_t off = ((p * 16 + brow) * KV_STRIDE + bcol + j * 16) * 2;
                uint32_t h0, h1, h2, h3, l0, l1, l2, l3;
                LDMX4(h0, h1, h2, h3, vb + off);
                LDMX4(l0, l1, l2, l3, vb + KV_TILE_B + off);
                uint32_t bfh0[2] = {h0, h1}, bfh1[2] = {h2, h3};
                uint32_t bfl0[2] = {l0, l1}, bfl1[2] = {l2, l3};
                MMA16816(s[2*p],   qh[j], bfh0);
                MMA16816(s[2*p],   qh[j], bfl0);
                MMA16816(s[2*p],   ql[j], bfh0);
                MMA16816(s[2*p+1], qh[j], bfh1);
                MMA16816(s[2*p+1], qh[j], bfl1);
                MMA16816(s[2*p+1], ql[j], bfh1);
            }
        }

        // ---- pos gather + scale + mask bias ----
        const int kc0 = kt * 64 + (lane & 3) * 2;
#pragma unroll
        for (int ni = 0; ni < 8; ni++) {
            int kc = kc0 + ni * 8;
            float2 bias = *(const float2*)(mb + kc);
            int d0 = kc - qr0;
            int r00 = min(max(d0,     -LPOS), LPOS) + LPOS;
            int r01 = min(max(d0 + 1, -LPOS), LPOS) + LPOS;
            int r10 = min(max(d0 - 8, -LPOS), LPOS) + LPOS;
            int r11 = min(max(d0 - 7, -LPOS), LPOS) + LPOS;
            s[ni][0] = (s[ni][0] + qpr0[r00]) * INV_SCALE + bias.x;
            s[ni][1] = (s[ni][1] + qpr0[r01]) * INV_SCALE + bias.y;
            s[ni][2] = (s[ni][2] + qpr1[r10]) * INV_SCALE + bias.x;
            s[ni][3] = (s[ni][3] + qpr1[r11]) * INV_SCALE + bias.y;
        }

        // ---- online softmax (rows: qr0 and qr0+8) ----
        float mx0 = s[0][0], mx1 = s[0][2];
#pragma unroll
        for (int ni = 0; ni < 8; ni++) {
            mx0 = fmaxf(mx0, fmaxf(s[ni][0], s[ni][1]));
            mx1 = fmaxf(mx1, fmaxf(s[ni][2], s[ni][3]));
        }
        mx0 = fmaxf(mx0, __shfl_xor_sync(0xffffffffu, mx0, 1));
        mx0 = fmaxf(mx0, __shfl_xor_sync(0xffffffffu, mx0, 2));
        mx1 = fmaxf(mx1, __shfl_xor_sync(0xffffffffu, mx1, 1));
        mx1 = fmaxf(mx1, __shfl_xor_sync(0xffffffffu, mx1, 2));
        float mn0 = fmaxf(mrow0, mx0), mn1 = fmaxf(mrow1, mx1);
        float a0 = __expf(mrow0 - mn0), a1 = __expf(mrow1 - mn1);
        mrow0 = mn0; mrow1 = mn1;
        float sum0 = 0.0f, sum1 = 0.0f;
#pragma unroll
        for (int ni = 0; ni < 8; ni++) {
            s[ni][0] = __expf(s[ni][0] - mn0); sum0 += s[ni][0];
            s[ni][1] = __expf(s[ni][1] - mn0); sum0 += s[ni][1];
            s[ni][2] = __expf(s[ni][2] - mn1); sum1 += s[ni][2];
            s[ni][3] = __expf(s[ni][3] - mn1); sum1 += s[ni][3];
        }
        sum0 += __shfl_xor_sync(0xffffffffu, sum0, 1);
        sum0 += __shfl_xor_sync(0xffffffffu, sum0, 2);
        sum1 += __shfl_xor_sync(0xffffffffu, sum1, 1);
        sum1 += __shfl_xor_sync(0xffffffffu, sum1, 2);
        lrow0 = lrow0 * a0 + sum0;
        lrow1 = lrow1 * a1 + sum1;
#pragma unroll
        for (int ni = 0; ni < 8; ni++) {
            o[ni][0] *= a0; o[ni][1] *= a0;
            o[ni][2] *= a1; o[ni][3] *= a1;
        }

        // ---- O += P V  (P split hi/lo in registers) ----
#pragma unroll
        for (int j = 0; j < 4; j++) {
            uint32_t ph[4], pl[4];
            ph[0] = pack_bf16(s[2*j][0],   s[2*j][1]);
            ph[1] = pack_bf16(s[2*j][2],   s[2*j][3]);
            ph[2] = pack_bf16(s[2*j+1][0], s[2*j+1][1]);
            ph[3] = pack_bf16(s[2*j+1][2], s[2*j+1][3]);
            pl[0] = pack_bf16(s[2*j][0]   - bf16lo_f(ph[0]), s[2*j][1]   - bf16hi_f(ph[0]));
            pl[1] = pack_bf16(s[2*j][2]   - bf16lo_f(ph[1]), s[2*j][3]   - bf16hi_f(ph[1]));
            pl[2] = pack_bf16(s[2*j+1][0] - bf16lo_f(ph[2]), s[2*j+1][1] - bf16hi_f(ph[2]));
            pl[3] = pack_bf16(s[2*j+1][2] - bf16lo_f(ph[3]), s[2*j+1][3] - bf16hi_f(ph[3]));
#pragma unroll
            for (int dg = 0; dg < 4; dg++) {
                uint32_t off = ((j * 16 + vrow) * KV_STRIDE + dg * 16 + vcol) * 2;
                uint32_t vh0, vh1, vh2, vh3, vl0, vl1, vl2, vl3;
                LDMX4T(vh0, vh1, vh2, vh3, vb + 2 * KV_TILE_B + off);
                LDMX4T(vl0, vl1, vl2, vl3, vb + 3 * KV_TILE_B + off);
                uint32_t bh0[2] = {vh0, vh1}, bh1[2] = {vh2, vh3};
                uint32_t bl0[2] = {vl0, vl1}, bl1[2] = {vl2, vl3};
                MMA16816(o[2*dg],   ph, bh0);
                MMA16816(o[2*dg],   ph, bl0);
                MMA16816(o[2*dg],   pl, bh0);
                MMA16816(o[2*dg+1], ph, bh1);
                MMA16816(o[2*dg+1], ph, bl1);
                MMA16816(o[2*dg+1], pl, bh1);
            }
        }
    }

    // ---- epilogue: normalize, split to bf16 hi/lo ----
    float inv0 = 1.0f / lrow0, inv1 = 1.0f / lrow1;
    const size_t obase0 = (size_t)(bT + qr0) * DDIM + hoff;
    const size_t obase1 = obase0 + (size_t)8 * DDIM;
#pragma unroll
    for (int ni = 0; ni < 8; ni++) {
        int dc = ni * 8 + (lane & 3) * 2;
        float f0 = o[ni][0] * inv0, f1 = o[ni][1] * inv0;
        float f2 = o[ni][2] * inv1, f3 = o[ni][3] * inv1;
        uint32_t h0 = pack_bf16(f0, f1);
        uint32_t h1 = pack_bf16(f2, f3);
        *(uint32_t*)(Ohi + obase0 + dc) = h0;
        *(uint32_t*)(Olo + obase0 + dc) = pack_bf16(f0 - bf16lo_f(h0), f1 - bf16hi_f(h0));
        *(uint32_t*)(Ohi + obase1 + dc) = h1;
        *(uint32_t*)(Olo + obase1 + dc) = pack_bf16(f2 - bf16lo_f(h1), f3 - bf16hi_f(h1));
    }
}

// ============================================================
// host launcher
// ============================================================
extern "C" void kernel_launch(void* const* d_in, const int* in_sizes, int n_in,
                              void* d_out, int out_size)
{
    const float* x_q = (const float*)d_in[0];
    const float* x_k = (const float*)d_in[1];
    const float* x_v = (const float*)d_in[2];
    const unsigned char* mask_raw = (const unsigned char*)d_in[3];
    const float* Wq = (const float*)d_in[4];
    const float* Wk = (const float*)d_in[5];
    const float* Wv = (const float*)d_in[6];
    const float* Wo = (const float*)d_in[7];
    const float* pos_emb = (const float*)d_in[8];
    float* out = (float*)d_out;

    void* p;
    cudaGetSymbolAddress(&p, g_Q);   float* Qb = (float*)p;
    cudaGetSymbolAddress(&p, g_Ahi); __nv_bfloat16* Ahi = (__nv_bfloat16*)p;
    cudaGetSymbolAddress(&p, g_Alo); __nv_bfloat16* Alo = (__nv_bfloat16*)p;
    cudaGetSymbolAddress(&p, g_Bhi); __nv_bfloat16* Bhi = (__nv_bfloat16*)p;
    cudaGetSymbolAddress(&p, g_Blo); __nv_bfloat16* Blo = (__nv_bfloat16*)p;
    cudaGetSymbolAddress(&p, g_Qhi); __nv_bfloat16* Qhi = (__nv_bfloat16*)p;
    cudaGetSymbolAddress(&p, g_Qlo); __nv_bfloat16* Qlo = (__nv_bfloat16*)p;
    cudaGetSymbolAddress(&p, g_Khi); __nv_bfloat16* Khi = (__nv_bfloat16*)p;
    cudaGetSymbolAddress(&p, g_Klo); __nv_bfloat16* Klo = (__nv_bfloat16*)p;
    cudaGetSymbolAddress(&p, g_Vhi); __nv_bfloat16* Vhi = (__nv_bfloat16*)p;
    cudaGetSymbolAddress(&p, g_Vlo); __nv_bfloat16* Vlo = (__nv_bfloat16*)p;

    cudaFuncSetAttribute(qp_kernel, cudaFuncAttributeMaxDynamicSharedMemorySize, QP_SMEM);
    cudaFuncSetAttribute(gemm_mma,  cudaFuncAttributeMaxDynamicSharedMemorySize, GM_SMEM);
    cudaFuncSetAttribute(attn_tc,   cudaFuncAttributeMaxDynamicSharedMemorySize, ATC_SMEM);

    const int M = BSZ*TLEN, N = DDIM;
    const int n4A = (BSZ*TLEN*DDIM) / 4;
    const int n4W = (DDIM*DDIM) / 4;
    dim3 gt(N/128, M/128);   // (8, 32)

    mask_prep<<<1, 256>>>(mask_raw);

    // Q = x_q @ Wq^T   (fp32 for qp_kernel + bf16 split for attention)
    split_bf16<<<n4A/256, 256>>>(x_q, Ahi, Alo, n4A);
    split_bf16<<<n4W/256, 256>>>(Wq,  Bhi, Blo, n4W);
    gemm_mma<<<gt, 256, GM_SMEM>>>(Ahi, Alo, Bhi, Blo, Qb, Qhi, Qlo);

    // K = x_k @ Wk^T   (bf16 split only)
    split_bf16<<<n4A/256, 256>>>(x_k, Ahi, Alo, n4A);
    split_bf16<<<n4W/256, 256>>>(Wk,  Bhi, Blo, n4W);
    gemm_mma<<<gt, 256, GM_SMEM>>>(Ahi, Alo, Bhi, Blo, nullptr, Khi, Klo);

    // V = x_v @ Wv^T   (bf16 split only)
    split_bf16<<<n4A/256, 256>>>(x_v, Ahi, Alo, n4A);
    split_bf16<<<n4W/256, 256>>>(Wv,  Bhi, Blo, n4W);
    gemm_mma<<<gt, 256, GM_SMEM>>>(Ahi, Alo, Bhi, Blo, nullptr, Vhi, Vlo);

    qp_kernel<<<BSZ*NH*(TLEN/64), 256, QP_SMEM>>>(pos_emb);

    // attention -> writes hi/lo split directly into Wo-GEMM A buffers
    attn_tc<<<BSZ*NH*(TLEN/128), 256, ATC_SMEM>>>(Ahi, Alo);

    // out = O @ Wo^T
    split_bf16<<<n4W/256, 256>>>(Wo, Bhi, Blo, n4W);
    gemm_mma<<<gt, 256, GM_SMEM>>>(Ahi, Alo, Bhi, Blo, out, nullptr, nullptr);
}

// round 13
// speedup vs baseline: 1.9377x; 1.0422x over previous
#include <cuda_runtime.h>
#include <cuda_bf16.h>
#include <math.h>
#include <stdint.h>

// Problem constants
#define BSZ   4
#define TLEN  1024
#define DDIM  1024
#define NH    16
#define DH    64
#define LPOS  128
#define NPOS  257            // 2*L+1
#define QPS   272            // padded stride for Qp rows
#define INV_SCALE 0.125f     // 1/sqrt(D/H) = 1/8

// -------- device scratch (no allocations allowed) --------
__device__ float g_Q [BSZ*TLEN*DDIM];          // fp32 Q (for qp_kernel)
__device__ float g_Qp[BSZ*NH*TLEN*QPS];
__device__ float g_maskbias[BSZ*TLEN];         // 0 or -1e30
// input splits
__device__ __nv_bfloat16 g_XQhi[BSZ*TLEN*DDIM];
__device__ __nv_bfloat16 g_XQlo[BSZ*TLEN*DDIM];
__device__ __nv_bfloat16 g_XKhi[BSZ*TLEN*DDIM];
__device__ __nv_bfloat16 g_XKlo[BSZ*TLEN*DDIM];
__device__ __nv_bfloat16 g_XVhi[BSZ*TLEN*DDIM];
__device__ __nv_bfloat16 g_XVlo[BSZ*TLEN*DDIM];
// weight splits
__device__ __nv_bfloat16 g_WQhi[DDIM*DDIM];
__device__ __nv_bfloat16 g_WQlo[DDIM*DDIM];
__device__ __nv_bfloat16 g_WKhi[DDIM*DDIM];
__device__ __nv_bfloat16 g_WKlo[DDIM*DDIM];
__device__ __nv_bfloat16 g_WVhi[DDIM*DDIM];
__device__ __nv_bfloat16 g_WVlo[DDIM*DDIM];
__device__ __nv_bfloat16 g_WOhi[DDIM*DDIM];
__device__ __nv_bfloat16 g_WOlo[DDIM*DDIM];
// projection outputs (split)
__device__ __nv_bfloat16 g_Qhi[BSZ*TLEN*DDIM];
__device__ __nv_bfloat16 g_Qlo[BSZ*TLEN*DDIM];
__device__ __nv_bfloat16 g_Khi[BSZ*TLEN*DDIM];
__device__ __nv_bfloat16 g_Klo[BSZ*TLEN*DDIM];
__device__ __nv_bfloat16 g_Vhi[BSZ*TLEN*DDIM];
__device__ __nv_bfloat16 g_Vlo[BSZ*TLEN*DDIM];

// ============================================================
// small helpers
// ============================================================
__device__ __forceinline__ uint32_t pack_bf16(float lo, float hi) {
    uint32_t d;
    asm("cvt.rn.bf16x2.f32 %0, %1, %2;" : "=r"(d) : "f"(hi), "f"(lo));
    return d;
}
__device__ __forceinline__ float bf16lo_f(uint32_t u) { return __uint_as_float(u << 16); }
__device__ __forceinline__ float bf16hi_f(uint32_t u) { return __uint_as_float(u & 0xffff0000u); }

// ============================================================
// mask_prep: normalize mask (int32-widened bool OR byte bool) -> float bias
// ============================================================
__global__ void mask_prep(const unsigned char* __restrict__ mraw)
{
    __shared__ int s_bytefmt;
    if (threadIdx.x == 0) s_bytefmt = 0;
    __syncthreads();

    int local = 0;
    for (int i = threadIdx.x; i < BSZ*TLEN; i += blockDim.x)
        if ((i & 3) != 0 && mraw[i] != 0) local = 1;
    if (local) atomicOr(&s_bytefmt, 1);
    __syncthreads();

    if (s_bytefmt) {
        for (int i = threadIdx.x; i < BSZ*TLEN; i += blockDim.x)
            g_maskbias[i] = mraw[i] ? -1e30f : 0.0f;
    } else {
        const int* mi = (const int*)mraw;
        for (int i = threadIdx.x; i < BSZ*TLEN; i += blockDim.x)
            g_maskbias[i] = mi[i] ? -1e30f : 0.0f;
    }
}

// ============================================================
// split_bf16: x(fp32) -> hi(bf16) + lo(bf16), vectorized by 4
// ============================================================
__global__ void __launch_bounds__(256) split_bf16(
    const float* __restrict__ x, __nv_bfloat16* __restrict__ hi,
    __nv_bfloat16* __restrict__ lo, int n4)
{
    int i = blockIdx.x * blockDim.x + threadIdx.x;
    if (i >= n4) return;
    float4 v = ((const float4*)x)[i];
    uint32_t h0 = pack_bf16(v.x, v.y);
    uint32_t h1 = pack_bf16(v.z, v.w);
    uint32_t l0 = pack_bf16(v.x - bf16lo_f(h0), v.y - bf16hi_f(h0));
    uint32_t l1 = pack_bf16(v.z - bf16lo_f(h1), v.w - bf16hi_f(h1));
    ((uint2*)hi)[i] = make_uint2(h0, h1);
    ((uint2*)lo)[i] = make_uint2(l0, l1);
}

// ============================================================
// mma.sync helpers (base sm_103 features)
// ============================================================
#define LDMX4(r0, r1, r2, r3, addr) \
    asm volatile("ldmatrix.sync.aligned.m8n8.x4.shared.b16 {%0,%1,%2,%3}, [%4];" \
        : "=r"(r0), "=r"(r1), "=r"(r2), "=r"(r3) : "r"(addr))

#define LDMX4T(r0, r1, r2, r3, addr) \
    asm volatile("ldmatrix.sync.aligned.m8n8.x4.trans.shared.b16 {%0,%1,%2,%3}, [%4];" \
        : "=r"(r0), "=r"(r1), "=r"(r2), "=r"(r3) : "r"(addr))

#define MMA16816(c, a, b) \
    asm volatile("mma.sync.aligned.m16n8k16.row.col.f32.bf16.bf16.f32 " \
        "{%0,%1,%2,%3}, {%4,%5,%6,%7}, {%8,%9}, {%0,%1,%2,%3};" \
        : "+f"((c)[0]), "+f"((c)[1]), "+f"((c)[2]), "+f"((c)[3]) \
        : "r"((a)[0]), "r"((a)[1]), "r"((a)[2]), "r"((a)[3]), \
          "r"((b)[0]), "r"((b)[1]))

// ============================================================
// Tensor-core split-bf16 GEMM NT body (3-stage cp.async pipeline):
//   out = (Ahi+Alo)[M,K] * (Bhi+Blo)[N,K]^T   (hi*hi + hi*lo + lo*hi)
// ============================================================
#define GEMM_BK      32
#define T_STRIDE     40
#define T_BYTES      (128*T_STRIDE*2)   // 10240
#define BUF_BYTES    (4*T_BYTES)        // 40960
#define GM_SMEM      (3*BUF_BYTES)      // 122880

__device__ __forceinline__ void gm_load_chunk(
    uint32_t sbuf,
    const __nv_bfloat16* __restrict__ Ahi, const __nv_bfloat16* __restrict__ Alo,
    const __nv_bfloat16* __restrict__ Bhi, const __nv_bfloat16* __restrict__ Blo,
    int m0, int n0, int k0, int tid)
{
#pragma unroll
    for (int j = 0; j < 8; j++) {
        int i = tid + j * 256;
        int t = i >> 9, idx = i & 511, row = idx >> 2, seg = idx & 3;
        uint32_t dst = sbuf + t * T_BYTES + row * (T_STRIDE*2) + seg * 16;
        const __nv_bfloat16* s = (t == 0) ? Ahi : (t == 1) ? Alo : (t == 2) ? Bhi : Blo;
        int gr = ((t < 2) ? m0 : n0) + row;
        const void* src = s + (size_t)gr * DDIM + k0 + seg * 8;
        asm volatile("cp.async.cg.shared.global [%0], [%1], 16;"
                     :: "r"(dst), "l"(src) : "memory");
    }
    asm volatile("cp.async.commit_group;" ::: "memory");
}

__device__ __forceinline__ void gemm_body(
    const __nv_bfloat16* __restrict__ Ahi, const __nv_bfloat16* __restrict__ Alo,
    const __nv_bfloat16* __restrict__ Bhi, const __nv_bfloat16* __restrict__ Blo,
    float* __restrict__ C,
    __nv_bfloat16* __restrict__ Chi, __nv_bfloat16* __restrict__ Clo)
{
    extern __shared__ __align__(128) char smc[];
    const uint32_t smb = (uint32_t)__cvta_generic_to_shared(smc);
    const int tid = threadIdx.x, lane = tid & 31, wid = tid >> 5;
    const int wm = wid & 3;
    const int warp_n = wid >> 2;
    const int m0 = blockIdx.y * 128, n0 = blockIdx.x * 128;

    float acc[2][8][4];
#pragma unroll
    for (int mi = 0; mi < 2; mi++)
#pragma unroll
        for (int ni = 0; ni < 8; ni++)
#pragma unroll
            for (int r = 0; r < 4; r++) acc[mi][ni][r] = 0.0f;

    const int sel = lane >> 3, rowl = lane & 7;
    const int arow = wm * 32 + rowl + (sel & 1) * 8;
    const int acol = (sel >> 1) * 8;
    const int brow = warp_n * 64 + rowl + (sel >> 1) * 8;
    const int bcol = (sel & 1) * 8;

    // 3-stage prologue: chunks 0,1 in flight
    gm_load_chunk(smb,             Ahi, Alo, Bhi, Blo, m0, n0, 0,        tid);
    gm_load_chunk(smb + BUF_BYTES, Ahi, Alo, Bhi, Blo, m0, n0, GEMM_BK,  tid);

    const int NCH = DDIM / GEMM_BK;   // 32
    for (int ch = 0; ch < NCH; ch++) {
        if (ch < NCH - 1)
            asm volatile("cp.async.wait_group 1;" ::: "memory");
        else
            asm volatile("cp.async.wait_group 0;" ::: "memory");
        __syncthreads();
        if (ch + 2 < NCH) {
            int nb = (ch + 2) % 3;
            gm_load_chunk(smb + nb * BUF_BYTES,
                          Ahi, Alo, Bhi, Blo, m0, n0, (ch + 2) * GEMM_BK, tid);
        }
        const uint32_t tb = smb + (ch % 3) * BUF_BYTES;
#pragma unroll
        for (int ks = 0; ks < 2; ks++) {
            uint32_t ah[2][4], al[2][4], bh[8][2], bl[8][2];
#pragma unroll
            for (int mi = 0; mi < 2; mi++) {
                uint32_t off = ((arow + mi * 16) * T_STRIDE + acol + ks * 16) * 2;
                LDMX4(ah[mi][0], ah[mi][1], ah[mi][2], ah[mi][3], tb + off);
                LDMX4(al[mi][0], al[mi][1], al[mi][2], al[mi][3], tb + T_BYTES + off);
            }
#pragma unroll
            for (int p = 0; p < 4; p++) {
                uint32_t off = ((brow + p * 16) * T_STRIDE + bcol + ks * 16) * 2;
                LDMX4(bh[2*p][0], bh[2*p][1], bh[2*p+1][0], bh[2*p+1][1],
                      tb + 2 * T_BYTES + off);
                LDMX4(bl[2*p][0], bl[2*p][1], bl[2*p+1][0], bl[2*p+1][1],
                      tb + 3 * T_BYTES + off);
            }
#pragma unroll
            for (int mi = 0; mi < 2; mi++)
#pragma unroll
                for (int ni = 0; ni < 8; ni++) {
                    MMA16816(acc[mi][ni], ah[mi], bh[ni]);
                    MMA16816(acc[mi][ni], ah[mi], bl[ni]);
                    MMA16816(acc[mi][ni], al[mi], bh[ni]);
                }
        }
    }

    // epilogue: fp32 (optional) + bf16 hi/lo split (optional)
    const int g = lane >> 2, t4 = lane & 3;
#pragma unroll
    for (int mi = 0; mi < 2; mi++) {
        const int r = m0 + wm * 32 + mi * 16 + g;
#pragma unroll
        for (int ni = 0; ni < 8; ni++) {
            const int col = n0 + warp_n * 64 + ni * 8 + t4 * 2;
            const size_t i0 = (size_t)r * DDIM + col;
            const size_t i1 = (size_t)(r + 8) * DDIM + col;
            float v0 = acc[mi][ni][0], v1 = acc[mi][ni][1];
            float v2 = acc[mi][ni][2], v3 = acc[mi][ni][3];
            if (C) {
                *(float2*)&C[i0] = make_float2(v0, v1);
                *(float2*)&C[i1] = make_float2(v2, v3);
            }
            if (Chi) {
                uint32_t h0 = pack_bf16(v0, v1);
                uint32_t h1 = pack_bf16(v2, v3);
                *(uint32_t*)(Chi + i0) = h0;
                *(uint32_t*)(Chi + i1) = h1;
                *(uint32_t*)(Clo + i0) =
                    pack_bf16(v0 - bf16lo_f(h0), v1 - bf16hi_f(h0));
                *(uint32_t*)(Clo + i1) =
                    pack_bf16(v2 - bf16lo_f(h1), v3 - bf16hi_f(h1));
            }
        }
    }
}

// fused Q/K/V projection: blockIdx.z selects operands (uniform per CTA)
__global__ void __launch_bounds__(256, 1) gemm_proj()
{
    const __nv_bfloat16 *Ah, *Al, *Bh, *Bl;
    float* C;
    __nv_bfloat16 *Ch, *Cl;
    if (blockIdx.z == 0) {
        Ah = g_XQhi; Al = g_XQlo; Bh = g_WQhi; Bl = g_WQlo;
        C = g_Q; Ch = g_Qhi; Cl = g_Qlo;
    } else if (blockIdx.z == 1) {
        Ah = g_XKhi; Al = g_XKlo; Bh = g_WKhi; Bl = g_WKlo;
        C = nullptr; Ch = g_Khi; Cl = g_Klo;
    } else {
        Ah = g_XVhi; Al = g_XVlo; Bh = g_WVhi; Bl = g_WVlo;
        C = nullptr; Ch = g_Vhi; Cl = g_Vlo;
    }
    gemm_body(Ah, Al, Bh, Bl, C, Ch, Cl);
}

// final output GEMM
__global__ void __launch_bounds__(256, 1) gemm_out(
    const __nv_bfloat16* __restrict__ Ahi, const __nv_bfloat16* __restrict__ Alo,
    float* __restrict__ C)
{
    gemm_body(Ahi, Alo, g_WOhi, g_WOlo, C, nullptr, nullptr);
}

// ============================================================
// Qp[b,h,q,r] = sum_d Q[b,q,h*DH+d] * pos_emb[r,d]
// ============================================================
#define QP_SMEM ((64*64 + NPOS*65) * 4)
__global__ void __launch_bounds__(256) qp_kernel(const float* __restrict__ pos_emb)
{
    extern __shared__ float sm[];
    float* Qs = sm;              // [q][d] stride 64
    float* Ps = sm + 64*64;      // [r][d] stride 65

    const int blk = blockIdx.x;
    const int qt = blk & 15, h = (blk >> 4) & 15, b = blk >> 8;
    const int q0 = qt * 64;
    const int tid = threadIdx.x;

    for (int i = tid; i < 64*64; i += 256) {
        int q = i >> 6, d = i & 63;
        Qs[q*64 + d] = g_Q[(size_t)(b*TLEN + q0 + q)*DDIM + h*DH + d];
    }
    for (int i = tid; i < NPOS*DH; i += 256) {
        int r = i >> 6, d = i & 63;
        Ps[r*65 + d] = pos_emb[i];
    }
    __syncthreads();

    const int rowbase = (b*NH + h)*TLEN + q0;
    for (int idx = tid; idx < 64*NPOS; idx += 256) {
        int q = idx / NPOS;
        int r = idx - q*NPOS;
        const float* qr = Qs + q*64;
        const float* pr = Ps + r*65;
        float s = 0.0f;
#pragma unroll 16
        for (int d = 0; d < 64; d++) s = fmaf(qr[d], pr[d], s);
        g_Qp[(size_t)(rowbase + q)*QPS + r] = s;
    }
}

// ============================================================
// Tensor-core flash attention (3-stage KV pipeline):
//  - CTA: 128 q rows of one (b,h); 8 warps, each m16.
//  - S = Qh*Kh^T + Qh*Kl^T + Ql*Kh^T
//  - P split hi/lo in regs -> PV = Ph*Vh + Ph*Vl + Pl*Vh
//  - epilogue writes bf16 hi/lo into the Wo-GEMM A-buffers
// ============================================================
#define KV_STRIDE 72
#define KV_TILE_B (64*KV_STRIDE*2)     // 9216
#define KV_BUF    (4*KV_TILE_B)        // 36864
#define ATQ_OFF   (3*KV_BUF)           // 110592
#define Q_TILE_B  (128*KV_STRIDE*2)    // 18432
#define ATC_SMEM  (ATQ_OFF + 2*Q_TILE_B)  // 147456

__device__ __forceinline__ void at_load_kv(uint32_t sbuf,
    int bT, int hoff, int k0, int tid)
{
#pragma unroll
    for (int j = 0; j < 8; j++) {
        int i = tid + j * 256;
        int t = i >> 9, idx = i & 511, row = idx >> 3, seg = idx & 7;
        uint32_t dst = sbuf + t * KV_TILE_B + row * (KV_STRIDE*2) + seg * 16;
        const __nv_bfloat16* s = (t == 0) ? g_Khi : (t == 1) ? g_Klo
                               : (t == 2) ? g_Vhi : g_Vlo;
        const void* src = s + (size_t)(bT + k0 + row) * DDIM + hoff + seg * 8;
        asm volatile("cp.async.cg.shared.global [%0], [%1], 16;"
                     :: "r"(dst), "l"(src) : "memory");
    }
    asm volatile("cp.async.commit_group;" ::: "memory");
}

__global__ void __launch_bounds__(256) attn_tc(
    __nv_bfloat16* __restrict__ Ohi, __nv_bfloat16* __restrict__ Olo)
{
    extern __shared__ __align__(128) char smc[];
    const uint32_t smb = (uint32_t)__cvta_generic_to_shared(smc);
    const int tid = threadIdx.x, lane = tid & 31, w = tid >> 5;
    const int qt = blockIdx.x & 7, h = (blockIdx.x >> 3) & 15, b = blockIdx.x >> 7;
    const int q0 = qt * 128, bT = b * TLEN, hoff = h * DH;

    const int rowl = lane & 7, sel = lane >> 3;
    const int arow = rowl + (sel & 1) * 8, acol = (sel >> 1) * 8;
    const int brow = rowl + (sel >> 1) * 8, bcol = (sel & 1) * 8;
    const int vrow = (sel & 1) * 8 + rowl, vcol = (sel >> 1) * 8;

    // stage Q hi/lo (128x64) into dedicated region (group 0)
#pragma unroll
    for (int j = 0; j < 8; j++) {
        int i = tid + j * 256;
        int t = i >> 10, idx = i & 1023, row = idx >> 3, seg = idx & 7;
        uint32_t dst = smb + ATQ_OFF + t * Q_TILE_B + row * (KV_STRIDE*2) + seg * 16;
        const __nv_bfloat16* s = t ? g_Qlo : g_Qhi;
        const void* src = s + (size_t)(bT + q0 + row) * DDIM + hoff + seg * 8;
        asm volatile("cp.async.cg.shared.global [%0], [%1], 16;"
                     :: "r"(dst), "l"(src) : "memory");
    }
    asm volatile("cp.async.commit_group;" ::: "memory");
    // prefetch KV tiles 0,1 (groups 1,2)
    at_load_kv(smb,          bT, hoff, 0,  tid);
    at_load_kv(smb + KV_BUF, bT, hoff, 64, tid);

    // wait for Q (oldest group), load Q fragments once
    asm volatile("cp.async.wait_group 2;" ::: "memory");
    __syncthreads();
    uint32_t qh[4][4], ql[4][4];
#pragma unroll
    for (int j = 0; j < 4; j++) {
        uint32_t off = ATQ_OFF + ((w * 16 + arow) * KV_STRIDE + acol + j * 16) * 2;
        LDMX4(qh[j][0], qh[j][1], qh[j][2], qh[j][3], smb + off);
        LDMX4(ql[j][0], ql[j][1], ql[j][2], ql[j][3], smb + Q_TILE_B + off);
    }

    float o[8][4];
#pragma unroll
    for (int ni = 0; ni < 8; ni++)
#pragma unroll
        for (int r = 0; r < 4; r++) o[ni][r] = 0.0f;
    float mrow0 = -1e30f, mrow1 = -1e30f, lrow0 = 0.0f, lrow1 = 0.0f;

    const int qr0 = q0 + w * 16 + (lane >> 2);
    const float* qpr0 = g_Qp + ((size_t)(b*NH + h)*TLEN + qr0) * QPS;
    const float* qpr1 = qpr0 + 8 * QPS;
    const float* mb = g_maskbias + bT;

    for (int kt = 0; kt < 16; kt++) {
        if (kt < 15)
            asm volatile("cp.async.wait_group 1;" ::: "memory");
        else
            asm volatile("cp.async.wait_group 0;" ::: "memory");
        __syncthreads();
        if (kt + 2 < 16)
            at_load_kv(smb + ((kt + 2) % 3) * KV_BUF, bT, hoff, (kt + 2) * 64, tid);
        const uint32_t vb = smb + (kt % 3) * KV_BUF;

        // ---- S = Q K^T ----
        float s[8][4];
#pragma unroll
        for (int ni = 0; ni < 8; ni++)
#pragma unroll
            for (int r = 0; r < 4; r++) s[ni][r] = 0.0f;
#pragma unroll
        for (int j = 0; j < 4; j++) {
#pragma unroll
            for (int p = 0; p < 4; p++) {
                uint32_t off = ((p * 16 + brow) * KV_STRIDE + bcol + j * 16) * 2;
                uint32_t h0, h1, h2, h3, l0, l1, l2, l3;
                LDMX4(h0, h1, h2, h3, vb + off);
                LDMX4(l0, l1, l2, l3, vb + KV_TILE_B + off);
                uint32_t bfh0[2] = {h0, h1}, bfh1[2] = {h2, h3};
                uint32_t bfl0[2] = {l0, l1}, bfl1[2] = {l2, l3};
                MMA16816(s[2*p],   qh[j], bfh0);
                MMA16816(s[2*p],   qh[j], bfl0);
                MMA16816(s[2*p],   ql[j], bfh0);
                MMA16816(s[2*p+1], qh[j], bfh1);
                MMA16816(s[2*p+1], qh[j], bfl1);
                MMA16816(s[2*p+1], ql[j], bfh1);
            }
        }

        // ---- pos gather + scale + mask bias ----
        const int kc0 = kt * 64 + (lane & 3) * 2;
#pragma unroll
        for (int ni = 0; ni < 8; ni++) {
            int kc = kc0 + ni * 8;
            float2 bias = *(const float2*)(mb + kc);
            int d0 = kc - qr0;
            int r00 = min(max(d0,     -LPOS), LPOS) + LPOS;
            int r01 = min(max(d0 + 1, -LPOS), LPOS) + LPOS;
            int r10 = min(max(d0 - 8, -LPOS), LPOS) + LPOS;
            int r11 = min(max(d0 - 7, -LPOS), LPOS) + LPOS;
            s[ni][0] = (s[ni][0] + qpr0[r00]) * INV_SCALE + bias.x;
            s[ni][1] = (s[ni][1] + qpr0[r01]) * INV_SCALE + bias.y;
            s[ni][2] = (s[ni][2] + qpr1[r10]) * INV_SCALE + bias.x;
            s[ni][3] = (s[ni][3] + qpr1[r11]) * INV_SCALE + bias.y;
        }

        // ---- online softmax (rows: qr0 and qr0+8) ----
        float mx0 = s[0][0], mx1 = s[0][2];
#pragma unroll
        for (int ni = 0; ni < 8; ni++) {
            mx0 = fmaxf(mx0, fmaxf(s[ni][0], s[ni][1]));
            mx1 = fmaxf(mx1, fmaxf(s[ni][2], s[ni][3]));
        }
        mx0 = fmaxf(mx0, __shfl_xor_sync(0xffffffffu, mx0, 1));
        mx0 = fmaxf(mx0, __shfl_xor_sync(0xffffffffu, mx0, 2));
        mx1 = fmaxf(mx1, __shfl_xor_sync(0xffffffffu, mx1, 1));
        mx1 = fmaxf(mx1, __shfl_xor_sync(0xffffffffu, mx1, 2));
        float mn0 = fmaxf(mrow0, mx0), mn1 = fmaxf(mrow1, mx1);
        float a0 = __expf(mrow0 - mn0), a1 = __expf(mrow1 - mn1);
        mrow0 = mn0; mrow1 = mn1;
        float sum0 = 0.0f, sum1 = 0.0f;
#pragma unroll
        for (int ni = 0; ni < 8; ni++) {
            s[ni][0] = __expf(s[ni][0] - mn0); sum0 += s[ni][0];
            s[ni][1] = __expf(s[ni][1] - mn0); sum0 += s[ni][1];
            s[ni][2] = __expf(s[ni][2] - mn1); sum1 += s[ni][2];
            s[ni][3] = __expf(s[ni][3] - mn1); sum1 += s[ni][3];
        }
        sum0 += __shfl_xor_sync(0xffffffffu, sum0, 1);
        sum0 += __shfl_xor_sync(0xffffffffu, sum0, 2);
        sum1 += __shfl_xor_sync(0xffffffffu, sum1, 1);
        sum1 += __shfl_xor_sync(0xffffffffu, sum1, 2);
        lrow0 = lrow0 * a0 + sum0;
        lrow1 = lrow1 * a1 + sum1;
#pragma unroll
        for (int ni = 0; ni < 8; ni++) {
            o[ni][0] *= a0; o[ni][1] *= a0;
            o[ni][2] *= a1; o[ni][3] *= a1;
        }

        // ---- O += P V  (P split hi/lo in registers) ----
#pragma unroll
        for (int j = 0; j < 4; j++) {
            uint32_t ph[4], pl[4];
            ph[0] = pack_bf16(s[2*j][0],   s[2*j][1]);
            ph[1] = pack_bf16(s[2*j][2],   s[2*j][3]);
            ph[2] = pack_bf16(s[2*j+1][0], s[2*j+1][1]);
            ph[3] = pack_bf16(s[2*j+1][2], s[2*j+1][3]);
            pl[0] = pack_bf16(s[2*j][0]   - bf16lo_f(ph[0]), s[2*j][1]   - bf16hi_f(ph[0]));
            pl[1] = pack_bf16(s[2*j][2]   - bf16lo_f(ph[1]), s[2*j][3]   - bf16hi_f(ph[1]));
            pl[2] = pack_bf16(s[2*j+1][0] - bf16lo_f(ph[2]), s[2*j+1][1] - bf16hi_f(ph[2]));
            pl[3] = pack_bf16(s[2*j+1][2] - bf16lo_f(ph[3]), s[2*j+1][3] - bf16hi_f(ph[3]));
#pragma unroll
            for (int dg = 0; dg < 4; dg++) {
                uint32_t off = ((j * 16 + vrow) * KV_STRIDE + dg * 16 + vcol) * 2;
                uint32_t vh0, vh1, vh2, vh3, vl0, vl1, vl2, vl3;
                LDMX4T(vh0, vh1, vh2, vh3, vb + 2 * KV_TILE_B + off);
                LDMX4T(vl0, vl1, vl2, vl3, vb + 3 * KV_TILE_B + off);
                uint32_t bh0[2] = {vh0, vh1}, bh1[2] = {vh2, vh3};
                uint32_t bl0[2] = {vl0, vl1}, bl1[2] = {vl2, vl3};
                MMA16816(o[2*dg],   ph, bh0);
                MMA16816(o[2*dg],   ph, bl0);
                MMA16816(o[2*dg],   pl, bh0);
                MMA16816(o[2*dg+1], ph, bh1);
                MMA16816(o[2*dg+1], ph, bl1);
                MMA16816(o[2*dg+1], pl, bh1);
            }
        }
    }

    // ---- epilogue: normalize, split to bf16 hi/lo ----
    float inv0 = 1.0f / lrow0, inv1 = 1.0f / lrow1;
    const size_t obase0 = (size_t)(bT + qr0) * DDIM + hoff;
    const size_t obase1 = obase0 + (size_t)8 * DDIM;
#pragma unroll
    for (int ni = 0; ni < 8; ni++) {
        int dc = ni * 8 + (lane & 3) * 2;
        float f0 = o[ni][0] * inv0, f1 = o[ni][1] * inv0;
        float f2 = o[ni][2] * inv1, f3 = o[ni][3] * inv1;
        uint32_t h0 = pack_bf16(f0, f1);
        uint32_t h1 = pack_bf16(f2, f3);
        *(uint32_t*)(Ohi + obase0 + dc) = h0;
        *(uint32_t*)(Olo + obase0 + dc) = pack_bf16(f0 - bf16lo_f(h0), f1 - bf16hi_f(h0));
        *(uint32_t*)(Ohi + obase1 + dc) = h1;
        *(uint32_t*)(Olo + obase1 + dc) = pack_bf16(f2 - bf16lo_f(h1), f3 - bf16hi_f(h1));
    }
}

// ============================================================
// host launcher
// ============================================================
extern "C" void kernel_launch(void* const* d_in, const int* in_sizes, int n_in,
                              void* d_out, int out_size)
{
    const float* x_q = (const float*)d_in[0];
    const float* x_k = (const float*)d_in[1];
    const float* x_v = (const float*)d_in[2];
    const unsigned char* mask_raw = (const unsigned char*)d_in[3];
    const float* Wq = (const float*)d_in[4];
    const float* Wk = (const float*)d_in[5];
    const float* Wv = (const float*)d_in[6];
    const float* Wo = (const float*)d_in[7];
    const float* pos_emb = (const float*)d_in[8];
    float* out = (float*)d_out;

    void* p;
    __nv_bfloat16 *XQh, *XQl, *XKh, *XKl, *XVh, *XVl;
    __nv_bfloat16 *WQh, *WQl, *WKh, *WKl, *WVh, *WVl, *WOh, *WOl;
    cudaGetSymbolAddress(&p, g_XQhi); XQh = (__nv_bfloat16*)p;
    cudaGetSymbolAddress(&p, g_XQlo); XQl = (__nv_bfloat16*)p;
    cudaGetSymbolAddress(&p, g_XKhi); XKh = (__nv_bfloat16*)p;
    cudaGetSymbolAddress(&p, g_XKlo); XKl = (__nv_bfloat16*)p;
    cudaGetSymbolAddress(&p, g_XVhi); XVh = (__nv_bfloat16*)p;
    cudaGetSymbolAddress(&p, g_XVlo); XVl = (__nv_bfloat16*)p;
    cudaGetSymbolAddress(&p, g_WQhi); WQh = (__nv_bfloat16*)p;
    cudaGetSymbolAddress(&p, g_WQlo); WQl = (__nv_bfloat16*)p;
    cudaGetSymbolAddress(&p, g_WKhi); WKh = (__nv_bfloat16*)p;
    cudaGetSymbolAddress(&p, g_WKlo); WKl = (__nv_bfloat16*)p;
    cudaGetSymbolAddress(&p, g_WVhi); WVh = (__nv_bfloat16*)p;
    cudaGetSymbolAddress(&p, g_WVlo); WVl = (__nv_bfloat16*)p;
    cudaGetSymbolAddress(&p, g_WOhi); WOh = (__nv_bfloat16*)p;
    cudaGetSymbolAddress(&p, g_WOlo); WOl = (__nv_bfloat16*)p;

    cudaFuncSetAttribute(qp_kernel, cudaFuncAttributeMaxDynamicSharedMemorySize, QP_SMEM);
    cudaFuncSetAttribute(gemm_proj, cudaFuncAttributeMaxDynamicSharedMemorySize, GM_SMEM);
    cudaFuncSetAttribute(gemm_out,  cudaFuncAttributeMaxDynamicSharedMemorySize, GM_SMEM);
    cudaFuncSetAttribute(attn_tc,   cudaFuncAttributeMaxDynamicSharedMemorySize, ATC_SMEM);

    const int n4A = (BSZ*TLEN*DDIM) / 4;
    const int n4W = (DDIM*DDIM) / 4;

    mask_prep<<<1, 256>>>(mask_raw);

    // all splits upfront
    split_bf16<<<n4A/256, 256>>>(x_q, XQh, XQl, n4A);
    split_bf16<<<n4A/256, 256>>>(x_k, XKh, XKl, n4A);
    split_bf16<<<n4A/256, 256>>>(x_v, XVh, XVl, n4A);
    split_bf16<<<n4W/256, 256>>>(Wq, WQh, WQl, n4W);
    split_bf16<<<n4W/256, 256>>>(Wk, WKh, WKl, n4W);
    split_bf16<<<n4W/256, 256>>>(Wv, WVh, WVl, n4W);
    split_bf16<<<n4W/256, 256>>>(Wo, WOh, WOl, n4W);

    // fused Q/K/V projections (one launch, CTA backfill across z)
    gemm_proj<<<dim3(DDIM/128, (BSZ*TLEN)/128, 3), 256, GM_SMEM>>>();

    qp_kernel<<<BSZ*NH*(TLEN/64), 256, QP_SMEM>>>(pos_emb);

    // attention -> writes hi/lo split into XQ buffers (reused as Wo-GEMM A)
    attn_tc<<<BSZ*NH*(TLEN/128), 256, ATC_SMEM>>>(XQh, XQl);

    // out = O @ Wo^T
    gemm_out<<<dim3(DDIM/128, (BSZ*TLEN)/128), 256, GM_SMEM>>>(XQh, XQl, out);
}

// round 15
// speedup vs baseline: 2.9421x; 1.5183x over previous
#include <cuda_runtime.h>
#include <cuda_bf16.h>
#include <math.h>
#include <stdint.h>

// Problem constants
#define BSZ   4
#define TLEN  1024
#define DDIM  1024
#define NH    16
#define DH    64
#define LPOS  128
#define NPOS  257            // 2*L+1
#define QPS   272            // padded stride for Qp rows

// -------- device scratch (no allocations allowed) --------
__device__ float g_Qp[BSZ*NH*TLEN*QPS];
__device__ float g_maskbias[BSZ*TLEN];         // 0 or -1e30
// input splits
__device__ __nv_bfloat16 g_XQhi[BSZ*TLEN*DDIM];
__device__ __nv_bfloat16 g_XQlo[BSZ*TLEN*DDIM];
__device__ __nv_bfloat16 g_XKhi[BSZ*TLEN*DDIM];
__device__ __nv_bfloat16 g_XKlo[BSZ*TLEN*DDIM];
__device__ __nv_bfloat16 g_XVhi[BSZ*TLEN*DDIM];
__device__ __nv_bfloat16 g_XVlo[BSZ*TLEN*DDIM];
// weight splits
__device__ __nv_bfloat16 g_WQhi[DDIM*DDIM];
__device__ __nv_bfloat16 g_WQlo[DDIM*DDIM];
__device__ __nv_bfloat16 g_WKhi[DDIM*DDIM];
__device__ __nv_bfloat16 g_WKlo[DDIM*DDIM];
__device__ __nv_bfloat16 g_WVhi[DDIM*DDIM];
__device__ __nv_bfloat16 g_WVlo[DDIM*DDIM];
__device__ __nv_bfloat16 g_WOhi[DDIM*DDIM];
__device__ __nv_bfloat16 g_WOlo[DDIM*DDIM];
// projection outputs (split; Q pre-scaled by 1/8)
__device__ __nv_bfloat16 g_Qhi[BSZ*TLEN*DDIM];
__device__ __nv_bfloat16 g_Qlo[BSZ*TLEN*DDIM];
__device__ __nv_bfloat16 g_Khi[BSZ*TLEN*DDIM];
__device__ __nv_bfloat16 g_Klo[BSZ*TLEN*DDIM];
__device__ __nv_bfloat16 g_Vhi[BSZ*TLEN*DDIM];
__device__ __nv_bfloat16 g_Vlo[BSZ*TLEN*DDIM];

// ============================================================
// small helpers
// ============================================================
__device__ __forceinline__ uint32_t pack_bf16(float lo, float hi) {
    uint32_t d;
    asm("cvt.rn.bf16x2.f32 %0, %1, %2;" : "=r"(d) : "f"(hi), "f"(lo));
    return d;
}
__device__ __forceinline__ float bf16lo_f(uint32_t u) { return __uint_as_float(u << 16); }
__device__ __forceinline__ float bf16hi_f(uint32_t u) { return __uint_as_float(u & 0xffff0000u); }

// ============================================================
// mask_prep: normalize mask (int32-widened bool OR byte bool) -> float bias
// ============================================================
__global__ void mask_prep(const unsigned char* __restrict__ mraw)
{
    __shared__ int s_bytefmt;
    if (threadIdx.x == 0) s_bytefmt = 0;
    __syncthreads();

    int local = 0;
    for (int i = threadIdx.x; i < BSZ*TLEN; i += blockDim.x)
        if ((i & 3) != 0 && mraw[i] != 0) local = 1;
    if (local) atomicOr(&s_bytefmt, 1);
    __syncthreads();

    if (s_bytefmt) {
        for (int i = threadIdx.x; i < BSZ*TLEN; i += blockDim.x)
            g_maskbias[i] = mraw[i] ? -1e30f : 0.0f;
    } else {
        const int* mi = (const int*)mraw;
        for (int i = threadIdx.x; i < BSZ*TLEN; i += blockDim.x)
            g_maskbias[i] = mi[i] ? -1e30f : 0.0f;
    }
}

// ============================================================
// split_bf16: x(fp32) -> hi(bf16) + lo(bf16), vectorized by 4
// ============================================================
__global__ void __launch_bounds__(256) split_bf16(
    const float* __restrict__ x, __nv_bfloat16* __restrict__ hi,
    __nv_bfloat16* __restrict__ lo, int n4)
{
    int i = blockIdx.x * blockDim.x + threadIdx.x;
    if (i >= n4) return;
    float4 v = ((const float4*)x)[i];
    uint32_t h0 = pack_bf16(v.x, v.y);
    uint32_t h1 = pack_bf16(v.z, v.w);
    uint32_t l0 = pack_bf16(v.x - bf16lo_f(h0), v.y - bf16hi_f(h0));
    uint32_t l1 = pack_bf16(v.z - bf16lo_f(h1), v.w - bf16hi_f(h1));
    ((uint2*)hi)[i] = make_uint2(h0, h1);
    ((uint2*)lo)[i] = make_uint2(l0, l1);
}

// ============================================================
// mma.sync helpers (base sm_103 features)
// ============================================================
#define LDMX4(r0, r1, r2, r3, addr) \
    asm volatile("ldmatrix.sync.aligned.m8n8.x4.shared.b16 {%0,%1,%2,%3}, [%4];" \
        : "=r"(r0), "=r"(r1), "=r"(r2), "=r"(r3) : "r"(addr))

#define LDMX4T(r0, r1, r2, r3, addr) \
    asm volatile("ldmatrix.sync.aligned.m8n8.x4.trans.shared.b16 {%0,%1,%2,%3}, [%4];" \
        : "=r"(r0), "=r"(r1), "=r"(r2), "=r"(r3) : "r"(addr))

#define MMA16816(c, a, b) \
    asm volatile("mma.sync.aligned.m16n8k16.row.col.f32.bf16.bf16.f32 " \
        "{%0,%1,%2,%3}, {%4,%5,%6,%7}, {%8,%9}, {%0,%1,%2,%3};" \
        : "+f"((c)[0]), "+f"((c)[1]), "+f"((c)[2]), "+f"((c)[3]) \
        : "r"((a)[0]), "r"((a)[1]), "r"((a)[2]), "r"((a)[3]), \
          "r"((b)[0]), "r"((b)[1]))

// ============================================================
// Tensor-core split-bf16 GEMM NT body (2-stage pipeline, 2 CTA/SM):
//   out = (Ahi+Alo)[M,K] * (Bhi+Blo)[N,K]^T   (hi*hi + hi*lo + lo*hi)
// T_STRIDE=40 elems -> 80B rows: 16B-aligned (cp.async req) AND
// conflict-free ldmatrix. (36 elems = 72B broke cp.async alignment.)
// ============================================================
#define GEMM_BK      32
#define T_STRIDE     40
#define T_BYTES      (128*T_STRIDE*2)   // 10240
#define BUF_BYTES    (4*T_BYTES)        // 40960
#define GM_SMEM      (2*BUF_BYTES)      // 81920 -> 2 CTA/SM

__device__ __forceinline__ void gm_load_chunk(
    uint32_t sbuf,
    const __nv_bfloat16* __restrict__ Ahi, const __nv_bfloat16* __restrict__ Alo,
    const __nv_bfloat16* __restrict__ Bhi, const __nv_bfloat16* __restrict__ Blo,
    int m0, int n0, int k0, int tid)
{
#pragma unroll
    for (int j = 0; j < 8; j++) {
        int i = tid + j * 256;
        int t = i >> 9, idx = i & 511, row = idx >> 2, seg = idx & 3;
        uint32_t dst = sbuf + t * T_BYTES + row * (T_STRIDE*2) + seg * 16;
        const __nv_bfloat16* s = (t == 0) ? Ahi : (t == 1) ? Alo : (t == 2) ? Bhi : Blo;
        int gr = ((t < 2) ? m0 : n0) + row;
        const void* src = s + (size_t)gr * DDIM + k0 + seg * 8;
        asm volatile("cp.async.cg.shared.global [%0], [%1], 16;"
                     :: "r"(dst), "l"(src) : "memory");
    }
    asm volatile("cp.async.commit_group;" ::: "memory");
}

__device__ __forceinline__ void gemm_body(
    const __nv_bfloat16* __restrict__ Ahi, const __nv_bfloat16* __restrict__ Alo,
    const __nv_bfloat16* __restrict__ Bhi, const __nv_bfloat16* __restrict__ Blo,
    float* __restrict__ C,
    __nv_bfloat16* __restrict__ Chi, __nv_bfloat16* __restrict__ Clo,
    float cscale)
{
    extern __shared__ __align__(128) char smc[];
    const uint32_t smb = (uint32_t)__cvta_generic_to_shared(smc);
    const int tid = threadIdx.x, lane = tid & 31, wid = tid >> 5;
    const int wm = wid & 3;
    const int warp_n = wid >> 2;
    const int m0 = blockIdx.y * 128, n0 = blockIdx.x * 128;

    float acc[2][8][4];
#pragma unroll
    for (int mi = 0; mi < 2; mi++)
#pragma unroll
        for (int ni = 0; ni < 8; ni++)
#pragma unroll
            for (int r = 0; r < 4; r++) acc[mi][ni][r] = 0.0f;

    const int sel = lane >> 3, rowl = lane & 7;
    const int arow = wm * 32 + rowl + (sel & 1) * 8;
    const int acol = (sel >> 1) * 8;
    const int brow = warp_n * 64 + rowl + (sel >> 1) * 8;
    const int bcol = (sel & 1) * 8;

    gm_load_chunk(smb, Ahi, Alo, Bhi, Blo, m0, n0, 0, tid);

    const int NCH = DDIM / GEMM_BK;   // 32
    for (int ch = 0; ch < NCH; ch++) {
        asm volatile("cp.async.wait_group 0;" ::: "memory");
        __syncthreads();
        if (ch + 1 < NCH)
            gm_load_chunk(smb + ((ch + 1) & 1) * BUF_BYTES,
                          Ahi, Alo, Bhi, Blo, m0, n0, (ch + 1) * GEMM_BK, tid);
        const uint32_t tb = smb + (ch & 1) * BUF_BYTES;
#pragma unroll
        for (int ks = 0; ks < 2; ks++) {
            uint32_t ah[2][4], al[2][4];
#pragma unroll
            for (int mi = 0; mi < 2; mi++) {
                uint32_t off = ((arow + mi * 16) * T_STRIDE + acol + ks * 16) * 2;
                LDMX4(ah[mi][0], ah[mi][1], ah[mi][2], ah[mi][3], tb + off);
                LDMX4(al[mi][0], al[mi][1], al[mi][2], al[mi][3], tb + T_BYTES + off);
            }
            // per-p B fragment loads (keeps live regs low for 2 CTA/SM)
#pragma unroll
            for (int p = 0; p < 4; p++) {
                uint32_t off = ((brow + p * 16) * T_STRIDE + bcol + ks * 16) * 2;
                uint32_t bh0[2], bh1[2], bl0[2], bl1[2];
                LDMX4(bh0[0], bh0[1], bh1[0], bh1[1], tb + 2 * T_BYTES + off);
                LDMX4(bl0[0], bl0[1], bl1[0], bl1[1], tb + 3 * T_BYTES + off);
#pragma unroll
                for (int mi = 0; mi < 2; mi++) {
                    MMA16816(acc[mi][2*p],   ah[mi], bh0);
                    MMA16816(acc[mi][2*p],   ah[mi], bl0);
                    MMA16816(acc[mi][2*p],   al[mi], bh0);
                    MMA16816(acc[mi][2*p+1], ah[mi], bh1);
                    MMA16816(acc[mi][2*p+1], ah[mi], bl1);
                    MMA16816(acc[mi][2*p+1], al[mi], bh1);
                }
            }
        }
    }

    // epilogue: fp32 (optional) + bf16 hi/lo split (optional), scaled
    const int g = lane >> 2, t4 = lane & 3;
#pragma unroll
    for (int mi = 0; mi < 2; mi++) {
        const int r = m0 + wm * 32 + mi * 16 + g;
#pragma unroll
        for (int ni = 0; ni < 8; ni++) {
            const int col = n0 + warp_n * 64 + ni * 8 + t4 * 2;
            const size_t i0 = (size_t)r * DDIM + col;
            const size_t i1 = (size_t)(r + 8) * DDIM + col;
            float v0 = acc[mi][ni][0] * cscale, v1 = acc[mi][ni][1] * cscale;
            float v2 = acc[mi][ni][2] * cscale, v3 = acc[mi][ni][3] * cscale;
            if (C) {
                *(float2*)&C[i0] = make_float2(v0, v1);
                *(float2*)&C[i1] = make_float2(v2, v3);
            }
            if (Chi) {
                uint32_t h0 = pack_bf16(v0, v1);
                uint32_t h1 = pack_bf16(v2, v3);
                *(uint32_t*)(Chi + i0) = h0;
                *(uint32_t*)(Chi + i1) = h1;
                *(uint32_t*)(Clo + i0) =
                    pack_bf16(v0 - bf16lo_f(h0), v1 - bf16hi_f(h0));
                *(uint32_t*)(Clo + i1) =
                    pack_bf16(v2 - bf16lo_f(h1), v3 - bf16hi_f(h1));
            }
        }
    }
}

// fused Q/K/V projection: blockIdx.z selects operands (uniform per CTA)
// Q output is pre-scaled by 1/SCALE = 0.125 (exact power of 2)
__global__ void __launch_bounds__(256, 2) gemm_proj()
{
    const __nv_bfloat16 *Ah, *Al, *Bh, *Bl;
    __nv_bfloat16 *Ch, *Cl;
    float sc;
    if (blockIdx.z == 0) {
        Ah = g_XQhi; Al = g_XQlo; Bh = g_WQhi; Bl = g_WQlo;
        Ch = g_Qhi; Cl = g_Qlo; sc = 0.125f;
    } else if (blockIdx.z == 1) {
        Ah = g_XKhi; Al = g_XKlo; Bh = g_WKhi; Bl = g_WKlo;
        Ch = g_Khi; Cl = g_Klo; sc = 1.0f;
    } else {
        Ah = g_XVhi; Al = g_XVlo; Bh = g_WVhi; Bl = g_WVlo;
        Ch = g_Vhi; Cl = g_Vlo; sc = 1.0f;
    }
    gemm_body(Ah, Al, Bh, Bl, nullptr, Ch, Cl, sc);
}

// final output GEMM
__global__ void __launch_bounds__(256, 2) gemm_out(
    const __nv_bfloat16* __restrict__ Ahi, const __nv_bfloat16* __restrict__ Alo,
    float* __restrict__ C)
{
    gemm_body(Ahi, Alo, g_WOhi, g_WOlo, C, nullptr, nullptr, 1.0f);
}

// ============================================================
// qp via mma.sync: Qp[bh][q][r] = Qscaled[bh,q,:] . pos_emb[r,:]
// CTA: one (b,h), 128 q rows. N padded 257->264. K=64.
// smem: Qhi/Qlo tiles [128x64]@72, Phi/Plo [264x64]@72 (split on the fly)
// 72-elem stride = 144B rows: 16B-aligned + conflict-free.
// ============================================================
#define QPK_STR   72
#define QPK_QT_B  (128*QPK_STR*2)       // 18432
#define QPK_P_B   (264*QPK_STR*2)       // 38016
#define QPK_SMEM  (2*QPK_QT_B + 2*QPK_P_B)  // 112896

__global__ void __launch_bounds__(256, 2) qp_mma(const float* __restrict__ pos_emb)
{
    extern __shared__ __align__(128) char smc[];
    const uint32_t smb = (uint32_t)__cvta_generic_to_shared(smc);
    const uint32_t QH = 0, QL = QPK_QT_B, PH = 2*QPK_QT_B, PL = 2*QPK_QT_B + QPK_P_B;
    const int tid = threadIdx.x, lane = tid & 31, w = tid >> 5;
    const int q0 = blockIdx.x * 128;
    const int bh = blockIdx.y;            // b*NH + h
    const int b = bh >> 4, h = bh & 15;
    const int bT = b * TLEN, hoff = h * DH;

    // stage Q hi/lo via cp.async
#pragma unroll
    for (int j = 0; j < 8; j++) {
        int i = tid + j * 256;
        int t = i >> 10, idx = i & 1023, row = idx >> 3, seg = idx & 7;
        uint32_t dst = smb + (t ? QL : QH) + row * (QPK_STR*2) + seg * 16;
        const __nv_bfloat16* s = t ? g_Qlo : g_Qhi;
        const void* src = s + (size_t)(bT + q0 + row) * DDIM + hoff + seg * 8;
        asm volatile("cp.async.cg.shared.global [%0], [%1], 16;"
                     :: "r"(dst), "l"(src) : "memory");
    }
    asm volatile("cp.async.commit_group;" ::: "memory");

    // pos_emb: fp32 -> hi/lo split into smem, zero-pad rows 257..263
    for (int i = tid; i < 264*64; i += 256) {
        int r = i >> 6, d = i & 63;
        float v = (r < NPOS) ? pos_emb[r * 64 + d] : 0.0f;
        __nv_bfloat16 hv = __float2bfloat16(v);
        __nv_bfloat16 lv = __float2bfloat16(v - __bfloat162float(hv));
        uint32_t off = (r * QPK_STR + d) * 2;
        *(__nv_bfloat16*)(smc + PH + off) = hv;
        *(__nv_bfloat16*)(smc + PL + off) = lv;
    }
    asm volatile("cp.async.wait_group 0;" ::: "memory");
    __syncthreads();

    // A fragments (Q rows w*16..w*16+15, K=64)
    const int rowl = lane & 7, sel = lane >> 3;
    const int arow = rowl + (sel & 1) * 8, acol = (sel >> 1) * 8;
    uint32_t qh[4][4], ql[4][4];
#pragma unroll
    for (int j = 0; j < 4; j++) {
        uint32_t off = ((w * 16 + arow) * QPK_STR + acol + j * 16) * 2;
        LDMX4(qh[j][0], qh[j][1], qh[j][2], qh[j][3], smb + QH + off);
        LDMX4(ql[j][0], ql[j][1], ql[j][2], ql[j][3], smb + QL + off);
    }

    const int g = lane >> 2, t4 = lane & 3;
    const int qr0 = q0 + w * 16 + g;
    const size_t rb0 = ((size_t)bh * TLEN + qr0) * QPS;
    const size_t rb1 = rb0 + (size_t)8 * QPS;

    // 33 n-chunks of 8 r-values
    for (int nc = 0; nc < 33; nc++) {
        float acc[4] = {0.0f, 0.0f, 0.0f, 0.0f};
        // B frags: 4 matrices = same 8 n-rows x k offsets 0/8/16/24
        uint32_t base = ((nc * 8 + rowl) * QPK_STR + sel * 8) * 2;
        uint32_t bh0[2], bh1[2], bh2[2], bh3[2];
        uint32_t bl0[2], bl1[2], bl2[2], bl3[2];
        LDMX4(bh0[0], bh0[1], bh1[0], bh1[1], smb + PH + base);
        LDMX4(bh2[0], bh2[1], bh3[0], bh3[1], smb + PH + base + 64);
        LDMX4(bl0[0], bl0[1], bl1[0], bl1[1], smb + PL + base);
        LDMX4(bl2[0], bl2[1], bl3[0], bl3[1], smb + PL + base + 64);
        MMA16816(acc, qh[0], bh0); MMA16816(acc, qh[0], bl0); MMA16816(acc, ql[0], bh0);
        MMA16816(acc, qh[1], bh1); MMA16816(acc, qh[1], bl1); MMA16816(acc, ql[1], bh1);
        MMA16816(acc, qh[2], bh2); MMA16816(acc, qh[2], bl2); MMA16816(acc, ql[2], bh2);
        MMA16816(acc, qh[3], bh3); MMA16816(acc, qh[3], bl3); MMA16816(acc, ql[3], bh3);
        int col = nc * 8 + t4 * 2;
        *(float2*)&g_Qp[rb0 + col] = make_float2(acc[0], acc[1]);
        *(float2*)&g_Qp[rb1 + col] = make_float2(acc[2], acc[3]);
    }
}

// ============================================================
// Tensor-core flash attention (3-stage KV pipeline, Q overlaid
// on buffer 2, 2 CTA/SM):
//  - CTA: 128 q rows of one (b,h); 8 warps, each m16.
//  - S = Qh*Kh^T + Qh*Kl^T + Ql*Kh^T   (Q pre-scaled by 1/8)
//  - P split hi/lo in regs -> PV = Ph*Vh + Ph*Vl + Pl*Vh
//  - epilogue writes bf16 hi/lo into the Wo-GEMM A-buffers
// ============================================================
#define KV_STRIDE 72
#define KV_TILE_B (64*KV_STRIDE*2)     // 9216 (144B rows: aligned)
#define KV_BUF    (4*KV_TILE_B)        // 36864
#define Q_TILE_B  (128*KV_STRIDE*2)    // 18432
#define ATQ_OFF   (2*KV_BUF)           // Q lives in buffer 2 initially
#define ATC_SMEM  (3*KV_BUF)           // 110592 -> 2 CTA/SM

__device__ __forceinline__ void at_load_kv(uint32_t sbuf,
    int bT, int hoff, int k0, int tid)
{
#pragma unroll
    for (int j = 0; j < 8; j++) {
        int i = tid + j * 256;
        int t = i >> 9, idx = i & 511, row = idx >> 3, seg = idx & 7;
        uint32_t dst = sbuf + t * KV_TILE_B + row * (KV_STRIDE*2) + seg * 16;
        const __nv_bfloat16* s = (t == 0) ? g_Khi : (t == 1) ? g_Klo
                               : (t == 2) ? g_Vhi : g_Vlo;
        const void* src = s + (size_t)(bT + k0 + row) * DDIM + hoff + seg * 8;
        asm volatile("cp.async.cg.shared.global [%0], [%1], 16;"
                     :: "r"(dst), "l"(src) : "memory");
    }
    asm volatile("cp.async.commit_group;" ::: "memory");
}

__global__ void __launch_bounds__(256, 2) attn_tc(
    __nv_bfloat16* __restrict__ Ohi, __nv_bfloat16* __restrict__ Olo)
{
    extern __shared__ __align__(128) char smc[];
    const uint32_t smb = (uint32_t)__cvta_generic_to_shared(smc);
    const int tid = threadIdx.x, lane = tid & 31, w = tid >> 5;
    const int qt = blockIdx.x & 7, h = (blockIdx.x >> 3) & 15, b = blockIdx.x >> 7;
    const int q0 = qt * 128, bT = b * TLEN, hoff = h * DH;

    const int rowl = lane & 7, sel = lane >> 3;
    const int arow = rowl + (sel & 1) * 8, acol = (sel >> 1) * 8;
    const int brow = rowl + (sel >> 1) * 8, bcol = (sel & 1) * 8;
    const int vrow = (sel & 1) * 8 + rowl, vcol = (sel >> 1) * 8;

    // stage Q hi/lo into buffer-2 region (group 0)
#pragma unroll
    for (int j = 0; j < 8; j++) {
        int i = tid + j * 256;
        int t = i >> 10, idx = i & 1023, row = idx >> 3, seg = idx & 7;
        uint32_t dst = smb + ATQ_OFF + t * Q_TILE_B + row * (KV_STRIDE*2) + seg * 16;
        const __nv_bfloat16* s = t ? g_Qlo : g_Qhi;
        const void* src = s + (size_t)(bT + q0 + row) * DDIM + hoff + seg * 8;
        asm volatile("cp.async.cg.shared.global [%0], [%1], 16;"
                     :: "r"(dst), "l"(src) : "memory");
    }
    asm volatile("cp.async.commit_group;" ::: "memory");
    // prefetch KV tiles 0,1 (groups 1,2)
    at_load_kv(smb,          bT, hoff, 0,  tid);
    at_load_kv(smb + KV_BUF, bT, hoff, 64, tid);

    // wait for Q (oldest group), register Q fragments, release buffer 2
    asm volatile("cp.async.wait_group 2;" ::: "memory");
    __syncthreads();
    uint32_t qh[4][4], ql[4][4];
#pragma unroll
    for (int j = 0; j < 4; j++) {
        uint32_t off = ATQ_OFF + ((w * 16 + arow) * KV_STRIDE + acol + j * 16) * 2;
        LDMX4(qh[j][0], qh[j][1], qh[j][2], qh[j][3], smb + off);
        LDMX4(ql[j][0], ql[j][1], ql[j][2], ql[j][3], smb + Q_TILE_B + off);
    }
    __syncthreads();   // all warps done reading Q; buffer 2 reusable

    float o[8][4];
#pragma unroll
    for (int ni = 0; ni < 8; ni++)
#pragma unroll
        for (int r = 0; r < 4; r++) o[ni][r] = 0.0f;
    float mrow0 = -1e30f, mrow1 = -1e30f, lrow0 = 0.0f, lrow1 = 0.0f;

    const int qr0 = q0 + w * 16 + (lane >> 2);
    const float* qpr0 = g_Qp + ((size_t)(b*NH + h)*TLEN + qr0) * QPS;
    const float* qpr1 = qpr0 + 8 * QPS;
    const float* mb = g_maskbias + bT;

    for (int kt = 0; kt < 16; kt++) {
        if (kt < 15)
            asm volatile("cp.async.wait_group 1;" ::: "memory");
        else
            asm volatile("cp.async.wait_group 0;" ::: "memory");
        __syncthreads();
        if (kt + 2 < 16)
            at_load_kv(smb + ((kt + 2) % 3) * KV_BUF, bT, hoff, (kt + 2) * 64, tid);
        const uint32_t vb = smb + (kt % 3) * KV_BUF;

        // ---- S = Q K^T (pre-scaled) ----
        float s[8][4];
#pragma unroll
        for (int ni = 0; ni < 8; ni++)
#pragma unroll
            for (int r = 0; r < 4; r++) s[ni][r] = 0.0f;
#pragma unroll
        for (int j = 0; j < 4; j++) {
#pragma unroll
            for (int p = 0; p < 4; p++) {
                uint32_t off = ((p * 16 + brow) * KV_STRIDE + bcol + j * 16) * 2;
                uint32_t h0, h1, h2, h3, l0, l1, l2, l3;
                LDMX4(h0, h1, h2, h3, vb + off);
                LDMX4(l0, l1, l2, l3, vb + KV_TILE_B + off);
                uint32_t bfh0[2] = {h0, h1}, bfh1[2] = {h2, h3};
                uint32_t bfl0[2] = {l0, l1}, bfl1[2] = {l2, l3};
                MMA16816(s[2*p],   qh[j], bfh0);
                MMA16816(s[2*p],   qh[j], bfl0);
                MMA16816(s[2*p],   ql[j], bfh0);
                MMA16816(s[2*p+1], qh[j], bfh1);
                MMA16816(s[2*p+1], qh[j], bfl1);
                MMA16816(s[2*p+1], ql[j], bfh1);
            }
        }

        // ---- pos gather (pre-scaled Qp) + mask bias ----
        const int kc0 = kt * 64 + (lane & 3) * 2;
#pragma unroll
        for (int ni = 0; ni < 8; ni++) {
            int kc = kc0 + ni * 8;
            float2 bias = *(const float2*)(mb + kc);
            int d0 = kc - qr0;
            int r00 = min(max(d0,     -LPOS), LPOS) + LPOS;
            int r01 = min(max(d0 + 1, -LPOS), LPOS) + LPOS;
            int r10 = min(max(d0 - 8, -LPOS), LPOS) + LPOS;
            int r11 = min(max(d0 - 7, -LPOS), LPOS) + LPOS;
            s[ni][0] = s[ni][0] + qpr0[r00] + bias.x;
            s[ni][1] = s[ni][1] + qpr0[r01] + bias.y;
            s[ni][2] = s[ni][2] + qpr1[r10] + bias.x;
            s[ni][3] = s[ni][3] + qpr1[r11] + bias.y;
        }

        // ---- online softmax (rows: qr0 and qr0+8) ----
        float mx0 = s[0][0], mx1 = s[0][2];
#pragma unroll
        for (int ni = 0; ni < 8; ni++) {
            mx0 = fmaxf(mx0, fmaxf(s[ni][0], s[ni][1]));
            mx1 = fmaxf(mx1, fmaxf(s[ni][2], s[ni][3]));
        }
        mx0 = fmaxf(mx0, __shfl_xor_sync(0xffffffffu, mx0, 1));
        mx0 = fmaxf(mx0, __shfl_xor_sync(0xffffffffu, mx0, 2));
        mx1 = fmaxf(mx1, __shfl_xor_sync(0xffffffffu, mx1, 1));
        mx1 = fmaxf(mx1, __shfl_xor_sync(0xffffffffu, mx1, 2));
        float mn0 = fmaxf(mrow0, mx0), mn1 = fmaxf(mrow1, mx1);
        float a0 = __expf(mrow0 - mn0), a1 = __expf(mrow1 - mn1);
        mrow0 = mn0; mrow1 = mn1;
        float sum0 = 0.0f, sum1 = 0.0f;
#pragma unroll
        for (int ni = 0; ni < 8; ni++) {
            s[ni][0] = __expf(s[ni][0] - mn0); sum0 += s[ni][0];
            s[ni][1] = __expf(s[ni][1] - mn0); sum0 += s[ni][1];
            s[ni][2] = __expf(s[ni][2] - mn1); sum1 += s[ni][2];
            s[ni][3] = __expf(s[ni][3] - mn1); sum1 += s[ni][3];
        }
        sum0 += __shfl_xor_sync(0xffffffffu, sum0, 1);
        sum0 += __shfl_xor_sync(0xffffffffu, sum0, 2);
        sum1 += __shfl_xor_sync(0xffffffffu, sum1, 1);
        sum1 += __shfl_xor_sync(0xffffffffu, sum1, 2);
        lrow0 = lrow0 * a0 + sum0;
        lrow1 = lrow1 * a1 + sum1;
#pragma unroll
        for (int ni = 0; ni < 8; ni++) {
            o[ni][0] *= a0; o[ni][1] *= a0;
            o[ni][2] *= a1; o[ni][3] *= a1;
        }

        // ---- O += P V  (P split hi/lo in registers) ----
#pragma unroll
        for (int j = 0; j < 4; j++) {
            uint32_t ph[4], pl[4];
            ph[0] = pack_bf16(s[2*j][0],   s[2*j][1]);
            ph[1] = pack_bf16(s[2*j][2],   s[2*j][3]);
            ph[2] = pack_bf16(s[2*j+1][0], s[2*j+1][1]);
            ph[3] = pack_bf16(s[2*j+1][2], s[2*j+1][3]);
            pl[0] = pack_bf16(s[2*j][0]   - bf16lo_f(ph[0]), s[2*j][1]   - bf16hi_f(ph[0]));
            pl[1] = pack_bf16(s[2*j][2]   - bf16lo_f(ph[1]), s[2*j][3]   - bf16hi_f(ph[1]));
            pl[2] = pack_bf16(s[2*j+1][0] - bf16lo_f(ph[2]), s[2*j+1][1] - bf16hi_f(ph[2]));
            pl[3] = pack_bf16(s[2*j+1][2] - bf16lo_f(ph[3]), s[2*j+1][3] - bf16hi_f(ph[3]));
#pragma unroll
            for (int dg = 0; dg < 4; dg++) {
                uint32_t off = ((j * 16 + vrow) * KV_STRIDE + dg * 16 + vcol) * 2;
                uint32_t vh0, vh1, vh2, vh3, vl0, vl1, vl2, vl3;
                LDMX4T(vh0, vh1, vh2, vh3, vb + 2 * KV_TILE_B + off);
                LDMX4T(vl0, vl1, vl2, vl3, vb + 3 * KV_TILE_B + off);
                uint32_t bh0[2] = {vh0, vh1}, bh1[2] = {vh2, vh3};
                uint32_t bl0[2] = {vl0, vl1}, bl1[2] = {vl2, vl3};
                MMA16816(o[2*dg],   ph, bh0);
                MMA16816(o[2*dg],   ph, bl0);
                MMA16816(o[2*dg],   pl, bh0);
                MMA16816(o[2*dg+1], ph, bh1);
                MMA16816(o[2*dg+1], ph, bl1);
                MMA16816(o[2*dg+1], pl, bh1);
            }
        }
    }

    // ---- epilogue: normalize, split to bf16 hi/lo ----
    float inv0 = 1.0f / lrow0, inv1 = 1.0f / lrow1;
    const size_t obase0 = (size_t)(bT + qr0) * DDIM + hoff;
    const size_t obase1 = obase0 + (size_t)8 * DDIM;
#pragma unroll
    for (int ni = 0; ni < 8; ni++) {
        int dc = ni * 8 + (lane & 3) * 2;
        float f0 = o[ni][0] * inv0, f1 = o[ni][1] * inv0;
        float f2 = o[ni][2] * inv1, f3 = o[ni][3] * inv1;
        uint32_t h0 = pack_bf16(f0, f1);
        uint32_t h1 = pack_bf16(f2, f3);
        *(uint32_t*)(Ohi + obase0 + dc) = h0;
        *(uint32_t*)(Olo + obase0 + dc) = pack_bf16(f0 - bf16lo_f(h0), f1 - bf16hi_f(h0));
        *(uint32_t*)(Ohi + obase1 + dc) = h1;
        *(uint32_t*)(Olo + obase1 + dc) = pack_bf16(f2 - bf16lo_f(h1), f3 - bf16hi_f(h1));
    }
}

// ============================================================
// host launcher
// ============================================================
extern "C" void kernel_launch(void* const* d_in, const int* in_sizes, int n_in,
                              void* d_out, int out_size)
{
    const float* x_q = (const float*)d_in[0];
    const float* x_k = (const float*)d_in[1];
    const float* x_v = (const float*)d_in[2];
    const unsigned char* mask_raw = (const unsigned char*)d_in[3];
    const float* Wq = (const float*)d_in[4];
    const float* Wk = (const float*)d_in[5];
    const float* Wv = (const float*)d_in[6];
    const float* Wo = (const float*)d_in[7];
    const float* pos_emb = (const float*)d_in[8];
    float* out = (float*)d_out;

    void* p;
    __nv_bfloat16 *XQh, *XQl, *XKh, *XKl, *XVh, *XVl;
    __nv_bfloat16 *WQh, *WQl, *WKh, *WKl, *WVh, *WVl, *WOh, *WOl;
    cudaGetSymbolAddress(&p, g_XQhi); XQh = (__nv_bfloat16*)p;
    cudaGetSymbolAddress(&p, g_XQlo); XQl = (__nv_bfloat16*)p;
    cudaGetSymbolAddress(&p, g_XKhi); XKh = (__nv_bfloat16*)p;
    cudaGetSymbolAddress(&p, g_XKlo); XKl = (__nv_bfloat16*)p;
    cudaGetSymbolAddress(&p, g_XVhi); XVh = (__nv_bfloat16*)p;
    cudaGetSymbolAddress(&p, g_XVlo); XVl = (__nv_bfloat16*)p;
    cudaGetSymbolAddress(&p, g_WQhi); WQh = (__nv_bfloat16*)p;
    cudaGetSymbolAddress(&p, g_WQlo); WQl = (__nv_bfloat16*)p;
    cudaGetSymbolAddress(&p, g_WKhi); WKh = (__nv_bfloat16*)p;
    cudaGetSymbolAddress(&p, g_WKlo); WKl = (__nv_bfloat16*)p;
    cudaGetSymbolAddress(&p, g_WVhi); WVh = (__nv_bfloat16*)p;
    cudaGetSymbolAddress(&p, g_WVlo); WVl = (__nv_bfloat16*)p;
    cudaGetSymbolAddress(&p, g_WOhi); WOh = (__nv_bfloat16*)p;
    cudaGetSymbolAddress(&p, g_WOlo); WOl = (__nv_bfloat16*)p;

    cudaFuncSetAttribute(gemm_proj, cudaFuncAttributeMaxDynamicSharedMemorySize, GM_SMEM);
    cudaFuncSetAttribute(gemm_out,  cudaFuncAttributeMaxDynamicSharedMemorySize, GM_SMEM);
    cudaFuncSetAttribute(qp_mma,    cudaFuncAttributeMaxDynamicSharedMemorySize, QPK_SMEM);
    cudaFuncSetAttribute(attn_tc,   cudaFuncAttributeMaxDynamicSharedMemorySize, ATC_SMEM);

    const int n4A = (BSZ*TLEN*DDIM) / 4;
    const int n4W = (DDIM*DDIM) / 4;

    mask_prep<<<1, 256>>>(mask_raw);

    // all splits upfront
    split_bf16<<<n4A/256, 256>>>(x_q, XQh, XQl, n4A);
    split_bf16<<<n4A/256, 256>>>(x_k, XKh, XKl, n4A);
    split_bf16<<<n4A/256, 256>>>(x_v, XVh, XVl, n4A);
    split_bf16<<<n4W/256, 256>>>(Wq, WQh, WQl, n4W);
    split_bf16<<<n4W/256, 256>>>(Wk, WKh, WKl, n4W);
    split_bf16<<<n4W/256, 256>>>(Wv, WVh, WVl, n4W);
    split_bf16<<<n4W/256, 256>>>(Wo, WOh, WOl, n4W);

    // fused Q/K/V projections (Q pre-scaled by 1/8)
    gemm_proj<<<dim3(DDIM/128, (BSZ*TLEN)/128, 3), 256, GM_SMEM>>>();

    // Qp = Qscaled @ pos_emb^T via mma
    qp_mma<<<dim3(TLEN/128, BSZ*NH), 256, QPK_SMEM>>>(pos_emb);

    // attention -> writes hi/lo split into XQ buffers (reused as Wo-GEMM A)
    attn_tc<<<BSZ*NH*(TLEN/128), 256, ATC_SMEM>>>(XQh, XQl);

    // out = O @ Wo^T
    gemm_out<<<dim3(DDIM/128, (BSZ*TLEN)/128), 256, GM_SMEM>>>(XQh, XQl, out);
}